// round 2
// baseline (speedup 1.0000x reference)
#include <cuda_runtime.h>
#include <math.h>
#include <stdint.h>

#define N_NODES 50000
#define N_EDGES 1600000
#define G 128
#define LG 16
#define PI_F 3.14159265358979323846f

typedef unsigned long long u64;

// ---- scratch (device globals; no allocation allowed) ----
__device__ __align__(16) float g_a[N_NODES * LG];        // n_s @ en_w[0:16]
__device__ __align__(16) float g_b[N_NODES * LG];        // n_s @ en_w[16:32] + en_b
__device__ __align__(16) float g_nv[N_NODES * 3 * LG];   // node_v @ nv_in_w
__device__ __align__(16) float g_acc_s[N_NODES * LG];    // segment sums
__device__ __align__(16) float g_acc_v[N_NODES * 3 * LG];

__device__ __forceinline__ float siluf(float x) { return x / (1.f + __expf(-x)); }

__device__ __forceinline__ void red4(float* p, float a, float b, float c, float d) {
    asm volatile("red.global.add.v4.f32 [%0], {%1,%2,%3,%4};"
                 :: "l"(p), "f"(a), "f"(b), "f"(c), "f"(d) : "memory");
}

// ---- packed f32x2 helpers (FFMA2 path, PTX-only) ----
__device__ __forceinline__ u64 ffma2(u64 a, u64 b, u64 c) {
    u64 d; asm("fma.rn.f32x2 %0,%1,%2,%3;" : "=l"(d) : "l"(a), "l"(b), "l"(c)); return d;
}
__device__ __forceinline__ u64 mul2(u64 a, u64 b) {
    u64 d; asm("mul.rn.f32x2 %0,%1,%2;" : "=l"(d) : "l"(a), "l"(b)); return d;
}
__device__ __forceinline__ u64 add2(u64 a, u64 b) {
    u64 d; asm("add.rn.f32x2 %0,%1,%2;" : "=l"(d) : "l"(a), "l"(b)); return d;
}
__device__ __forceinline__ u64 pk2(float x, float y) {
    u64 r; asm("mov.b64 %0,{%1,%2};" : "=l"(r) : "f"(x), "f"(y)); return r;
}
__device__ __forceinline__ float2 upk(u64 a) {
    float lo, hi; asm("mov.b64 {%0,%1},%2;" : "=f"(lo), "=f"(hi) : "l"(a));
    return make_float2(lo, hi);
}

// ============================================================================
// Kernel 1: node input projections (SMEM weights, staged rows) + acc zeroing
// 256 threads, 64 nodes/block. thread = (j = t&15, slot = t>>4), 4 passes.
// ============================================================================
#define K1_NPB 64
#define WPAD 130   // stride 130 == 2 mod 32 -> conflict-free float2 lanes

__global__ void __launch_bounds__(256) k_node_in(
    const float* __restrict__ node_s, const float* __restrict__ node_v,
    const float* __restrict__ ns_w, const float* __restrict__ ns_b,
    const float* __restrict__ nv_w, const float* __restrict__ en_w,
    const float* __restrict__ en_b)
{
    __shared__ __align__(16) float s_wsT[16 * WPAD];
    __shared__ __align__(16) float s_wvT[16 * WPAD];
    __shared__ __align__(16) float s_en[32 * 16];
    __shared__ __align__(16) float s_rows[K1_NPB * 128];
    __shared__ float s_sns[K1_NPB * 16];

    int t = threadIdx.x;
    int n0 = blockIdx.x * K1_NPB;

    // zero segment-sum accumulators (grid-stride, runs concurrently with loads)
    {
        float4* as4 = (float4*)g_acc_s;   // 200000 float4
        float4* av4 = (float4*)g_acc_v;   // 600000 float4
        int idx = blockIdx.x * 256 + t;
        int stride = gridDim.x * 256;
        for (int i = idx; i < 200000; i += stride) as4[i] = make_float4(0.f, 0.f, 0.f, 0.f);
        for (int i = idx; i < 600000; i += stride) av4[i] = make_float4(0.f, 0.f, 0.f, 0.f);
    }

    // weights -> SMEM (transposed: row j holds column j over g)
    for (int i = t; i < 2048; i += 256) {
        int gg = i >> 4, j = i & 15;
        s_wsT[j * WPAD + gg] = ns_w[i];
        s_wvT[j * WPAD + gg] = nv_w[i];
    }
    for (int i = t; i < 512; i += 256) s_en[i] = en_w[i];

    // stage scalar rows (contiguous block of 64 nodes)
    {
        const float4* src4 = (const float4*)(node_s + (size_t)n0 * 128);
        float4* dst4 = (float4*)s_rows;
        int nvalid = N_NODES - n0; if (nvalid > K1_NPB) nvalid = K1_NPB;
        int lim = nvalid * 32;
        for (int i = t; i < K1_NPB * 32; i += 256)
            dst4[i] = (i < lim) ? src4[i] : make_float4(0.f, 0.f, 0.f, 0.f);
    }
    __syncthreads();

    int j = t & 15, slot = t >> 4;
    const float2* w2s = (const float2*)(s_wsT + j * WPAD);
    const float2* w2v = (const float2*)(s_wvT + j * WPAD);

    #pragma unroll
    for (int p = 0; p < 4; p++) {
        int nl = slot + 16 * p;
        int n = n0 + nl;
        bool ok = (n < N_NODES);

        // scalar projection: dot(node_s[n], ns_w[:,j])
        const float4* r4 = (const float4*)(s_rows + nl * 128);
        float acc = 0.f;
        #pragma unroll
        for (int q = 0; q < 32; q++) {
            float4 r = r4[q];
            float2 wa = w2s[2 * q], wb = w2s[2 * q + 1];
            acc += r.x * wa.x + r.y * wa.y + r.z * wb.x + r.w * wb.y;
        }
        acc += __ldg(ns_b + j);
        s_sns[nl * 16 + j] = siluf(acc);

        // vector projections: 3 dots of 128
        if (ok) {
            #pragma unroll
            for (int x = 0; x < 3; x++) {
                const float4* v4 = (const float4*)(node_v + (size_t)n * 384 + x * 128);
                float av = 0.f;
                #pragma unroll
                for (int q = 0; q < 32; q++) {
                    float4 r = __ldg(v4 + q);
                    float2 wa = w2v[2 * q], wb = w2v[2 * q + 1];
                    av += r.x * wa.x + r.y * wa.y + r.z * wb.x + r.w * wb.y;
                }
                g_nv[(size_t)n * 48 + x * 16 + j] = av;
            }
        }
    }
    __syncthreads();

    // en_w pre-split: a = sns @ en_w[0:16], b = sns @ en_w[16:32] + en_b
    #pragma unroll
    for (int p = 0; p < 4; p++) {
        int nl = slot + 16 * p;
        int n = n0 + nl;
        if (n < N_NODES) {
            float a = 0.f, b = __ldg(en_b + j);
            #pragma unroll
            for (int k = 0; k < 16; k++) {
                float x = s_sns[nl * 16 + k];
                a += x * s_en[k * 16 + j];
                b += x * s_en[(16 + k) * 16 + j];
            }
            g_a[(size_t)n * 16 + j] = a;
            g_b[(size_t)n * 16 + j] = b;
        }
    }
}

// ============================================================================
// Kernel 2: per-edge fused chain, f32x2-packed matvecs, weights in SMEM
// ============================================================================
__global__ void __launch_bounds__(128) k_edge(
    const float* __restrict__ edge_s, const float* __restrict__ edge_v,
    const float* __restrict__ dist,   const float* __restrict__ vctr,
    const int* __restrict__ src,      const int* __restrict__ dst,
    const float* __restrict__ tp_w, const float* __restrict__ tp_b,
    const float* __restrict__ g1w,  const float* __restrict__ g1b,
    const float* __restrict__ g2w,  const float* __restrict__ g2b,
    const float* __restrict__ tvw,  const float* __restrict__ tvb,
    float* __restrict__ out_es, float* __restrict__ out_ev)
{
    __shared__ __align__(16) float s_tp[256], s_g1[256], s_g2[256], s_tv[768];
    __shared__ __align__(16) float s_tpb[16], s_g1b[16], s_g2b[16], s_tvb[48];
    int t = threadIdx.x;
    for (int i = t; i < 256; i += 128) { s_tp[i] = tp_w[i]; s_g1[i] = g1w[i]; s_g2[i] = g2w[i]; }
    for (int i = t; i < 768; i += 128) s_tv[i] = tvw[i];
    if (t < 16) { s_tpb[t] = tp_b[t]; s_g1b[t] = g1b[t]; s_g2b[t] = g2b[t]; }
    if (t < 48) s_tvb[t] = tvb[t];
    __syncthreads();

    int e = blockIdx.x * 128 + t;
    int s = src[e], d = dst[e];

    // edge_s row
    float esl[16];
    {
        const float4* p = (const float4*)(edge_s + (size_t)e * 16);
        #pragma unroll
        for (int i = 0; i < 4; i++) {
            float4 v = __ldg(p + i);
            esl[4 * i] = v.x; esl[4 * i + 1] = v.y; esl[4 * i + 2] = v.z; esl[4 * i + 3] = v.w;
        }
    }

    // tm = (edge_s @ tp_w + tp_b), packed
    u64 tm2[8];
    {
        const ulonglong2* bb = (const ulonglong2*)s_tpb;
        #pragma unroll
        for (int i = 0; i < 4; i++) { ulonglong2 v = bb[i]; tm2[2 * i] = v.x; tm2[2 * i + 1] = v.y; }
    }
    #pragma unroll
    for (int k = 0; k < 16; k++) {
        u64 xx = pk2(esl[k], esl[k]);
        const ulonglong2* w = (const ulonglong2*)(s_tp + k * 16);
        #pragma unroll
        for (int i = 0; i < 4; i++) {
            ulonglong2 wv = w[i];
            tm2[2 * i]     = ffma2(xx, wv.x, tm2[2 * i]);
            tm2[2 * i + 1] = ffma2(xx, wv.y, tm2[2 * i + 1]);
        }
    }
    // tm *= (a[src] + b[dst])
    {
        const ulonglong2* pa = (const ulonglong2*)(g_a + (size_t)s * 16);
        const ulonglong2* pb = (const ulonglong2*)(g_b + (size_t)d * 16);
        #pragma unroll
        for (int i = 0; i < 4; i++) {
            ulonglong2 va = pa[i], vb = pb[i];
            tm2[2 * i]     = mul2(tm2[2 * i],     add2(va.x, vb.x));
            tm2[2 * i + 1] = mul2(tm2[2 * i + 1], add2(va.y, vb.y));
        }
    }
    float tmx[16];
    #pragma unroll
    for (int i = 0; i < 8; i++) { float2 v = upk(tm2[i]); tmx[2 * i] = v.x; tmx[2 * i + 1] = v.y; }

    // h = silu(tm @ g1 + b1)
    u64 h2[8];
    {
        const ulonglong2* bb = (const ulonglong2*)s_g1b;
        #pragma unroll
        for (int i = 0; i < 4; i++) { ulonglong2 v = bb[i]; h2[2 * i] = v.x; h2[2 * i + 1] = v.y; }
    }
    #pragma unroll
    for (int k = 0; k < 16; k++) {
        u64 xx = pk2(tmx[k], tmx[k]);
        const ulonglong2* w = (const ulonglong2*)(s_g1 + k * 16);
        #pragma unroll
        for (int i = 0; i < 4; i++) {
            ulonglong2 wv = w[i];
            h2[2 * i]     = ffma2(xx, wv.x, h2[2 * i]);
            h2[2 * i + 1] = ffma2(xx, wv.y, h2[2 * i + 1]);
        }
    }
    float hx[16];
    #pragma unroll
    for (int i = 0; i < 8; i++) {
        float2 v = upk(h2[i]);
        hx[2 * i] = siluf(v.x); hx[2 * i + 1] = siluf(v.y);
    }

    // gt = h @ g2 + b2
    u64 gt2[8];
    {
        const ulonglong2* bb = (const ulonglong2*)s_g2b;
        #pragma unroll
        for (int i = 0; i < 4; i++) { ulonglong2 v = bb[i]; gt2[2 * i] = v.x; gt2[2 * i + 1] = v.y; }
    }
    #pragma unroll
    for (int k = 0; k < 16; k++) {
        u64 xx = pk2(hx[k], hx[k]);
        const ulonglong2* w = (const ulonglong2*)(s_g2 + k * 16);
        #pragma unroll
        for (int i = 0; i < 4; i++) {
            ulonglong2 wv = w[i];
            gt2[2 * i]     = ffma2(xx, wv.x, gt2[2 * i]);
            gt2[2 * i + 1] = ffma2(xx, wv.y, gt2[2 * i + 1]);
        }
    }

    float dd = __ldg(dist + e);
    float C = 0.5f * (__cosf(PI_F * dd * 0.1f) + 1.f) * (dd < 10.f ? 1.f : 0.f);

    float es[16];
    #pragma unroll
    for (int i = 0; i < 8; i++) {
        float2 v = upk(gt2[i]);
        es[2 * i]     = tmx[2 * i]     * (1.f / (1.f + __expf(-v.x))) * C;
        es[2 * i + 1] = tmx[2 * i + 1] * (1.f / (1.f + __expf(-v.y))) * C;
    }

    // edge_s_out + scatter
    {
        float4* po = (float4*)(out_es + (size_t)e * 16);
        #pragma unroll
        for (int i = 0; i < 4; i++) {
            float4 v;
            v.x = es[4 * i]     + esl[4 * i];
            v.y = es[4 * i + 1] + esl[4 * i + 1];
            v.z = es[4 * i + 2] + esl[4 * i + 2];
            v.w = es[4 * i + 3] + esl[4 * i + 3];
            po[i] = v;
        }
        float* pacc = g_acc_s + (size_t)d * 16;
        #pragma unroll
        for (int i = 0; i < 4; i++)
            red4(pacc + 4 * i, es[4 * i], es[4 * i + 1], es[4 * i + 2], es[4 * i + 3]);
    }

    // ter = (es @ tv_w + tv_b) * C, packed: [t16|e16|r16] -> ter2[0..7|8..15|16..23]
    u64 ter2[24];
    {
        const ulonglong2* bb = (const ulonglong2*)s_tvb;
        #pragma unroll
        for (int i = 0; i < 12; i++) { ulonglong2 v = bb[i]; ter2[2 * i] = v.x; ter2[2 * i + 1] = v.y; }
    }
    #pragma unroll
    for (int k = 0; k < 16; k++) {
        u64 xx = pk2(es[k], es[k]);
        const ulonglong2* w = (const ulonglong2*)(s_tv + k * 48);
        #pragma unroll
        for (int i = 0; i < 12; i++) {
            ulonglong2 wv = w[i];
            ter2[2 * i]     = ffma2(xx, wv.x, ter2[2 * i]);
            ter2[2 * i + 1] = ffma2(xx, wv.y, ter2[2 * i + 1]);
        }
    }
    {
        u64 CC = pk2(C, C);
        #pragma unroll
        for (int i = 0; i < 24; i++) ter2[i] = mul2(ter2[i], CC);
    }

    float vn0 = __ldg(vctr + (size_t)e * 3);
    float vn1 = __ldg(vctr + (size_t)e * 3 + 1);
    float vn2 = __ldg(vctr + (size_t)e * 3 + 2);

    #pragma unroll
    for (int x = 0; x < 3; x++) {
        float vnx = (x == 0) ? vn0 : (x == 1) ? vn1 : vn2;
        u64 vnxx = pk2(vnx, vnx);
        const ulonglong2* pe = (const ulonglong2*)(edge_v + (size_t)e * 48 + x * 16);
        const ulonglong2* pn = (const ulonglong2*)(g_nv + (size_t)s * 48 + x * 16);
        u64 evi[8], nvs[8];
        #pragma unroll
        for (int i = 0; i < 4; i++) {
            ulonglong2 a = __ldg(pe + i);
            ulonglong2 b = pn[i];
            evi[2 * i] = a.x; evi[2 * i + 1] = a.y;
            nvs[2 * i] = b.x; nvs[2 * i + 1] = b.y;
        }
        u64 evu[8];
        #pragma unroll
        for (int i = 0; i < 8; i++)
            evu[i] = ffma2(evi[i], ter2[i], ffma2(nvs[i], ter2[8 + i], mul2(vnxx, ter2[16 + i])));

        ulonglong2* po = (ulonglong2*)(out_ev + (size_t)e * 48 + x * 16);
        #pragma unroll
        for (int i = 0; i < 4; i++) {
            ulonglong2 o;
            o.x = add2(evu[2 * i], evi[2 * i]);
            o.y = add2(evu[2 * i + 1], evi[2 * i + 1]);
            po[i] = o;
        }
        float* pacc = g_acc_v + (size_t)d * 48 + x * 16;
        #pragma unroll
        for (int i = 0; i < 4; i++) {
            float2 a = upk(evu[2 * i]);
            float2 b = upk(evu[2 * i + 1]);
            red4(pacc + 4 * i, a.x, a.y, b.x, b.y);
        }
    }
}

// ============================================================================
// Kernel 3: node epilogue. 128 threads, 16 nodes/block, weights in SMEM.
// ============================================================================
#define K3_NPB 16
__global__ void __launch_bounds__(128) k_node_out(
    const float* __restrict__ node_s, const float* __restrict__ node_v,
    const float* __restrict__ onw,
    const float* __restrict__ w1, const float* __restrict__ b1,
    const float* __restrict__ w2, const float* __restrict__ b2,
    const float* __restrict__ gamma, const float* __restrict__ beta,
    const float* __restrict__ cns, float* __restrict__ out)
{
    __shared__ __align__(16) float s_w1[512], s_w2[2048], s_onw[2048];
    __shared__ float s_b1[16], s_b2[128], s_gam[128], s_bet[128], s_cns[128];
    __shared__ float sacc[16], snvn[16], sh[16], saccv[48];
    __shared__ float rs1[4], rs2[4];

    int t = threadIdx.x;
    for (int i = t; i < 512; i += 128) s_w1[i] = w1[i];
    for (int i = t; i < 2048; i += 128) { s_w2[i] = w2[i]; s_onw[i] = onw[i]; }
    if (t < 16) s_b1[t] = b1[t];
    s_b2[t] = b2[t]; s_gam[t] = gamma[t]; s_bet[t] = beta[t]; s_cns[t] = cns[t];
    __syncthreads();

    int n0 = blockIdx.x * K3_NPB;
    for (int it = 0; it < K3_NPB; it++) {
        int n = n0 + it;

        if (t < 16) sacc[t] = g_acc_s[(size_t)n * 16 + t];
        else if (t < 64) saccv[t - 16] = g_acc_v[(size_t)n * 48 + (t - 16)];
        else if (t < 80) {
            int l = t - 64;
            float a = g_nv[(size_t)n * 48 + l];
            float b = g_nv[(size_t)n * 48 + 16 + l];
            float c = g_nv[(size_t)n * 48 + 32 + l];
            snvn[l] = sqrtf(a * a + b * b + c * c);
        }
        __syncthreads();

        if (t < 16) {
            float acc = s_b1[t];
            #pragma unroll
            for (int k = 0; k < 16; k++) acc += sacc[k] * s_w1[k * 16 + t];
            #pragma unroll
            for (int k = 0; k < 16; k++) acc += snvn[k] * s_w1[(16 + k) * 16 + t];
            sh[t] = siluf(acc);
        }
        __syncthreads();

        float nsu = s_b2[t];
        #pragma unroll
        for (int l = 0; l < 16; l++) nsu += sh[l] * s_w2[l * 128 + t];
        float xv = nsu + node_s[(size_t)n * 128 + t];

        float s1 = xv, s2 = xv * xv;
        #pragma unroll
        for (int o = 16; o > 0; o >>= 1) {
            s1 += __shfl_down_sync(0xffffffffu, s1, o);
            s2 += __shfl_down_sync(0xffffffffu, s2, o);
        }
        if ((t & 31) == 0) { rs1[t >> 5] = s1; rs2[t >> 5] = s2; }
        __syncthreads();
        float ts1 = rs1[0] + rs1[1] + rs1[2] + rs1[3];
        float ts2 = rs2[0] + rs2[1] + rs2[2] + rs2[3];
        float mu = ts1 * (1.f / 128.f);
        float var = ts2 * (1.f / 128.f) - mu * mu;
        out[(size_t)n * 128 + t] = (xv - mu) * rsqrtf(var + 1e-5f) * s_gam[t] + s_bet[t];

        float a0 = 0.f, a1 = 0.f, a2 = 0.f;
        #pragma unroll
        for (int l = 0; l < 16; l++) {
            float w = s_onw[l * 128 + t];
            a0 += saccv[l] * w;
            a1 += saccv[16 + l] * w;
            a2 += saccv[32 + l] * w;
        }
        float v0 = a0 + node_v[(size_t)n * 384 + t];
        float v1 = a1 + node_v[(size_t)n * 384 + 128 + t];
        float v2 = a2 + node_v[(size_t)n * 384 + 256 + t];
        float vn = sqrtf(v0 * v0 + v1 * v1 + v2 * v2);
        float sc = s_cns[t] / (vn + 1e-8f);
        size_t base = 6400000ull + (size_t)n * 384;
        out[base + t]       = v0 * sc;
        out[base + 128 + t] = v1 * sc;
        out[base + 256 + t] = v2 * sc;
        __syncthreads();
    }
}

// ============================================================================
extern "C" void kernel_launch(void* const* d_in, const int* in_sizes, int n_in,
                              void* d_out, int out_size)
{
    const float* node_s  = (const float*)d_in[0];
    const float* node_v  = (const float*)d_in[1];
    const float* edge_s  = (const float*)d_in[2];
    const float* edge_v  = (const float*)d_in[3];
    const float* dist    = (const float*)d_in[4];
    const float* vctr    = (const float*)d_in[5];
    const int*   src     = (const int*)d_in[6];
    const int*   dst     = (const int*)d_in[7];
    const float* ns_in_w = (const float*)d_in[8];
    const float* ns_in_b = (const float*)d_in[9];
    const float* nv_in_w = (const float*)d_in[10];
    const float* en_w    = (const float*)d_in[11];
    const float* en_b    = (const float*)d_in[12];
    const float* tp_w    = (const float*)d_in[13];
    const float* tp_b    = (const float*)d_in[14];
    const float* gate_w1 = (const float*)d_in[15];
    const float* gate_b1 = (const float*)d_in[16];
    const float* gate_w2 = (const float*)d_in[17];
    const float* gate_b2 = (const float*)d_in[18];
    const float* tv_w    = (const float*)d_in[19];
    const float* tv_b    = (const float*)d_in[20];
    const float* out_nv_w= (const float*)d_in[21];
    const float* ons_w1  = (const float*)d_in[22];
    const float* ons_b1  = (const float*)d_in[23];
    const float* ons_w2  = (const float*)d_in[24];
    const float* ons_b2  = (const float*)d_in[25];
    const float* ln_gamma= (const float*)d_in[26];
    const float* ln_beta = (const float*)d_in[27];
    const float* cn_scale= (const float*)d_in[28];

    float* out = (float*)d_out;
    float* out_es = out + 25600000ull;
    float* out_ev = out + 51200000ull;

    k_node_in<<<(N_NODES + K1_NPB - 1) / K1_NPB, 256>>>(
        node_s, node_v, ns_in_w, ns_in_b, nv_in_w, en_w, en_b);
    k_edge<<<N_EDGES / 128, 128>>>(edge_s, edge_v, dist, vctr, src, dst,
                                   tp_w, tp_b, gate_w1, gate_b1, gate_w2, gate_b2,
                                   tv_w, tv_b, out_es, out_ev);
    k_node_out<<<N_NODES / K3_NPB, 128>>>(node_s, node_v, out_nv_w, ons_w1, ons_b1,
                                          ons_w2, ons_b2, ln_gamma, ln_beta, cn_scale, out);
}

// round 3
// speedup vs baseline: 1.0368x; 1.0368x over previous
#include <cuda_runtime.h>
#include <math.h>
#include <stdint.h>

#define N_NODES 50000
#define N_EDGES 1600000
#define G 128
#define LG 16
#define PI_F 3.14159265358979323846f

// ---- scratch (device globals; no allocation allowed) ----
__device__ __align__(16) float g_a[N_NODES * LG];        // n_s @ en_w[0:16]
__device__ __align__(16) float g_b[N_NODES * LG];        // n_s @ en_w[16:32] + en_b
__device__ __align__(16) float g_nv[N_NODES * 3 * LG];   // node_v @ nv_in_w
__device__ __align__(16) float g_acc_s[N_NODES * LG];    // segment sums
__device__ __align__(16) float g_acc_v[N_NODES * 3 * LG];

__device__ __forceinline__ float siluf(float x) { return x / (1.f + __expf(-x)); }

__device__ __forceinline__ void red4(float* p, float a, float b, float c, float d) {
    asm volatile("red.global.add.v4.f32 [%0], {%1,%2,%3,%4};"
                 :: "l"(p), "f"(a), "f"(b), "f"(c), "f"(d) : "memory");
}

// ============================================================================
// Kernel 1: node input projections. Persistent weights in SMEM, grid-stride
// over 16-node tiles. 256 threads = 16 j-lanes x 16 node slots. Low regs.
// ============================================================================
#define WPAD 130   // 130 mod 32 == 2 -> conflict-free float2 lanes across j
#define K1_TILES (N_NODES / 16)   // 3125 exactly

__global__ void __launch_bounds__(256) k_node_in(
    const float* __restrict__ node_s, const float* __restrict__ node_v,
    const float* __restrict__ ns_w, const float* __restrict__ ns_b,
    const float* __restrict__ nv_w, const float* __restrict__ en_w,
    const float* __restrict__ en_b)
{
    __shared__ __align__(16) float s_wsT[16 * WPAD];
    __shared__ __align__(16) float s_wvT[16 * WPAD];
    __shared__ __align__(16) float s_en[512];
    __shared__ float s_sns[16 * 16];
    __shared__ float s_nsb[16], s_enb[16];

    int t = threadIdx.x;

    // zero segment-sum accumulators (grid-stride)
    {
        float4* as4 = (float4*)g_acc_s;   // 200000 float4
        float4* av4 = (float4*)g_acc_v;   // 600000 float4
        int idx = blockIdx.x * 256 + t;
        int stride = gridDim.x * 256;
        for (int i = idx; i < 200000; i += stride) as4[i] = make_float4(0.f, 0.f, 0.f, 0.f);
        for (int i = idx; i < 600000; i += stride) av4[i] = make_float4(0.f, 0.f, 0.f, 0.f);
    }

    // weights -> SMEM once (transposed: row j holds column j over g)
    for (int i = t; i < 2048; i += 256) {
        int gg = i >> 4, j = i & 15;
        s_wsT[j * WPAD + gg] = ns_w[i];
        s_wvT[j * WPAD + gg] = nv_w[i];
    }
    for (int i = t; i < 512; i += 256) s_en[i] = en_w[i];
    if (t < 16) { s_nsb[t] = ns_b[t]; s_enb[t] = en_b[t]; }
    __syncthreads();

    int j = t & 15, slot = t >> 4;
    const float2* w2s = (const float2*)(s_wsT + j * WPAD);
    const float2* w2v = (const float2*)(s_wvT + j * WPAD);

    for (int tile = blockIdx.x; tile < K1_TILES; tile += gridDim.x) {
        int n = tile * 16 + slot;

        // scalar projection: dot(node_s[n], ns_w[:,j]) (row via LDG broadcast)
        {
            const float4* r4 = (const float4*)(node_s + (size_t)n * 128);
            float acc = s_nsb[j];
            #pragma unroll 8
            for (int q = 0; q < 32; q++) {
                float4 r = __ldg(r4 + q);
                float2 wa = w2s[2 * q], wb = w2s[2 * q + 1];
                acc += r.x * wa.x + r.y * wa.y + r.z * wb.x + r.w * wb.y;
            }
            s_sns[slot * 16 + j] = siluf(acc);
        }

        // vector projections
        #pragma unroll
        for (int x = 0; x < 3; x++) {
            const float4* v4 = (const float4*)(node_v + (size_t)n * 384 + x * 128);
            float av = 0.f;
            #pragma unroll 8
            for (int q = 0; q < 32; q++) {
                float4 r = __ldg(v4 + q);
                float2 wa = w2v[2 * q], wb = w2v[2 * q + 1];
                av += r.x * wa.x + r.y * wa.y + r.z * wb.x + r.w * wb.y;
            }
            g_nv[(size_t)n * 48 + x * 16 + j] = av;
        }
        __syncthreads();

        // en_w pre-split
        {
            float a = 0.f, b = s_enb[j];
            #pragma unroll
            for (int k = 0; k < 16; k++) {
                float x = s_sns[slot * 16 + k];
                a += x * s_en[k * 16 + j];
                b += x * s_en[(16 + k) * 16 + j];
            }
            g_a[(size_t)n * 16 + j] = a;
            g_b[(size_t)n * 16 + j] = b;
        }
        __syncthreads();
    }
}

// ============================================================================
// Kernel 2: per-edge fused chain (scalar FMA core), streaming cache hints so
// node tables (g_a/g_b/g_nv) stay L2-resident for the gathers.
// ============================================================================
__global__ void __launch_bounds__(128) k_edge(
    const float* __restrict__ edge_s, const float* __restrict__ edge_v,
    const float* __restrict__ dist,   const float* __restrict__ vctr,
    const int* __restrict__ src,      const int* __restrict__ dst,
    const float* __restrict__ tp_w, const float* __restrict__ tp_b,
    const float* __restrict__ g1w,  const float* __restrict__ g1b,
    const float* __restrict__ g2w,  const float* __restrict__ g2b,
    const float* __restrict__ tvw,  const float* __restrict__ tvb,
    float* __restrict__ out_es, float* __restrict__ out_ev)
{
    __shared__ __align__(16) float s_tp[256], s_g1[256], s_g2[256], s_tv[768];
    __shared__ float s_tpb[16], s_g1b[16], s_g2b[16], s_tvb[48];
    int t = threadIdx.x;
    for (int i = t; i < 256; i += 128) { s_tp[i] = tp_w[i]; s_g1[i] = g1w[i]; s_g2[i] = g2w[i]; }
    for (int i = t; i < 768; i += 128) s_tv[i] = tvw[i];
    if (t < 16) { s_tpb[t] = tp_b[t]; s_g1b[t] = g1b[t]; s_g2b[t] = g2b[t]; }
    if (t < 48) s_tvb[t] = tvb[t];
    __syncthreads();

    int e = blockIdx.x * 128 + t;

    int s = __ldcs(src + e), d = __ldcs(dst + e);
    float dd = __ldcs(dist + e);

    // gathers (want L2 hits) — issue early
    float en[16];
    {
        const float4* pa = (const float4*)(g_a + (size_t)s * 16);
        const float4* pb = (const float4*)(g_b + (size_t)d * 16);
        #pragma unroll
        for (int i = 0; i < 4; i++) {
            float4 va = __ldg(pa + i), vb = __ldg(pb + i);
            en[4 * i]     = va.x + vb.x; en[4 * i + 1] = va.y + vb.y;
            en[4 * i + 2] = va.z + vb.z; en[4 * i + 3] = va.w + vb.w;
        }
    }

    // edge_s row (streaming)
    float esl[16];
    {
        const float4* p = (const float4*)(edge_s + (size_t)e * 16);
        #pragma unroll
        for (int i = 0; i < 4; i++) {
            float4 v = __ldcs(p + i);
            esl[4 * i] = v.x; esl[4 * i + 1] = v.y; esl[4 * i + 2] = v.z; esl[4 * i + 3] = v.w;
        }
    }

    // tm = en * (edge_s @ tp_w + tp_b)
    float tm[16];
    #pragma unroll
    for (int jj = 0; jj < 16; jj++) tm[jj] = s_tpb[jj];
    #pragma unroll
    for (int k = 0; k < 16; k++) {
        float x = esl[k];
        #pragma unroll
        for (int jj = 0; jj < 16; jj++) tm[jj] += x * s_tp[k * 16 + jj];
    }
    #pragma unroll
    for (int jj = 0; jj < 16; jj++) tm[jj] *= en[jj];

    // h = silu(tm @ g1 + b1)
    float h[16];
    #pragma unroll
    for (int jj = 0; jj < 16; jj++) h[jj] = s_g1b[jj];
    #pragma unroll
    for (int k = 0; k < 16; k++) {
        float x = tm[k];
        #pragma unroll
        for (int jj = 0; jj < 16; jj++) h[jj] += x * s_g1[k * 16 + jj];
    }
    #pragma unroll
    for (int jj = 0; jj < 16; jj++) h[jj] = siluf(h[jj]);

    // gt = h @ g2 + b2
    float gt[16];
    #pragma unroll
    for (int jj = 0; jj < 16; jj++) gt[jj] = s_g2b[jj];
    #pragma unroll
    for (int k = 0; k < 16; k++) {
        float x = h[k];
        #pragma unroll
        for (int jj = 0; jj < 16; jj++) gt[jj] += x * s_g2[k * 16 + jj];
    }

    float C = 0.5f * (__cosf(PI_F * dd * 0.1f) + 1.f) * (dd < 10.f ? 1.f : 0.f);

    float es[16];
    #pragma unroll
    for (int jj = 0; jj < 16; jj++)
        es[jj] = tm[jj] * (1.f / (1.f + __expf(-gt[jj]))) * C;

    // edge_s_out = es + edge_s (esl re-materialized by compiler) ; scatter
    {
        float4* po = (float4*)(out_es + (size_t)e * 16);
        #pragma unroll
        for (int i = 0; i < 4; i++) {
            float4 v;
            v.x = es[4 * i]     + esl[4 * i];
            v.y = es[4 * i + 1] + esl[4 * i + 1];
            v.z = es[4 * i + 2] + esl[4 * i + 2];
            v.w = es[4 * i + 3] + esl[4 * i + 3];
            __stcs(po + i, v);
        }
        float* pacc = g_acc_s + (size_t)d * 16;
        #pragma unroll
        for (int i = 0; i < 4; i++)
            red4(pacc + 4 * i, es[4 * i], es[4 * i + 1], es[4 * i + 2], es[4 * i + 3]);
    }

    // ter = (es @ tv_w + tv_b) * C   [t16|e16|r16]
    float ter[48];
    #pragma unroll
    for (int jj = 0; jj < 48; jj++) ter[jj] = s_tvb[jj];
    #pragma unroll
    for (int k = 0; k < 16; k++) {
        float x = es[k];
        #pragma unroll
        for (int jj = 0; jj < 48; jj++) ter[jj] += x * s_tv[k * 48 + jj];
    }
    #pragma unroll
    for (int jj = 0; jj < 48; jj++) ter[jj] *= C;

    float vn0 = __ldcs(vctr + (size_t)e * 3);
    float vn1 = __ldcs(vctr + (size_t)e * 3 + 1);
    float vn2 = __ldcs(vctr + (size_t)e * 3 + 2);

    #pragma unroll
    for (int x = 0; x < 3; x++) {
        float vnx = (x == 0) ? vn0 : (x == 1) ? vn1 : vn2;
        float evi[16], nvs[16];
        {
            const float4* pe = (const float4*)(edge_v + (size_t)e * 48 + x * 16);
            const float4* pn = (const float4*)(g_nv + (size_t)s * 48 + x * 16);
            #pragma unroll
            for (int i = 0; i < 4; i++) {
                float4 a = __ldcs(pe + i);
                float4 b = __ldg(pn + i);
                evi[4 * i] = a.x; evi[4 * i + 1] = a.y; evi[4 * i + 2] = a.z; evi[4 * i + 3] = a.w;
                nvs[4 * i] = b.x; nvs[4 * i + 1] = b.y; nvs[4 * i + 2] = b.z; nvs[4 * i + 3] = b.w;
            }
        }
        float evu[16];
        #pragma unroll
        for (int jj = 0; jj < 16; jj++)
            evu[jj] = evi[jj] * ter[jj] + nvs[jj] * ter[16 + jj] + vnx * ter[32 + jj];

        float4* po = (float4*)(out_ev + (size_t)e * 48 + x * 16);
        #pragma unroll
        for (int i = 0; i < 4; i++) {
            float4 v;
            v.x = evu[4 * i]     + evi[4 * i];
            v.y = evu[4 * i + 1] + evi[4 * i + 1];
            v.z = evu[4 * i + 2] + evi[4 * i + 2];
            v.w = evu[4 * i + 3] + evi[4 * i + 3];
            __stcs(po + i, v);
        }
        float* pacc = g_acc_v + (size_t)d * 48 + x * 16;
        #pragma unroll
        for (int i = 0; i < 4; i++)
            red4(pacc + 4 * i, evu[4 * i], evu[4 * i + 1], evu[4 * i + 2], evu[4 * i + 3]);
    }
}

// ============================================================================
// Kernel 3: node epilogue. 256 threads = 2 nodes in parallel; weights in SMEM.
// ============================================================================
#define K3_NPB 16
__global__ void __launch_bounds__(256) k_node_out(
    const float* __restrict__ node_s, const float* __restrict__ node_v,
    const float* __restrict__ onw,
    const float* __restrict__ w1, const float* __restrict__ b1,
    const float* __restrict__ w2, const float* __restrict__ b2,
    const float* __restrict__ gamma, const float* __restrict__ beta,
    const float* __restrict__ cns, float* __restrict__ out)
{
    __shared__ __align__(16) float s_w1[512], s_w2[2048], s_onw[2048];
    __shared__ float s_b1[16], s_b2[128], s_gam[128], s_bet[128], s_cns[128];
    __shared__ float sacc[2][16], snvn[2][16], sh[2][16], saccv[2][48];
    __shared__ float rs1[2][4], rs2[2][4];

    int t = threadIdx.x;
    for (int i = t; i < 512; i += 256) s_w1[i] = w1[i];
    for (int i = t; i < 2048; i += 256) { s_w2[i] = w2[i]; s_onw[i] = onw[i]; }
    if (t < 16) s_b1[t] = b1[t];
    if (t < 128) { s_b2[t] = b2[t]; s_gam[t] = gamma[t]; s_bet[t] = beta[t]; s_cns[t] = cns[t]; }
    __syncthreads();

    int grp = t >> 7, tt = t & 127;
    int n0 = blockIdx.x * K3_NPB;

    for (int it = 0; it < K3_NPB; it += 2) {
        int n = n0 + it + grp;

        if (tt < 16) sacc[grp][tt] = g_acc_s[(size_t)n * 16 + tt];
        else if (tt < 64) saccv[grp][tt - 16] = g_acc_v[(size_t)n * 48 + (tt - 16)];
        else if (tt < 80) {
            int l = tt - 64;
            float a = g_nv[(size_t)n * 48 + l];
            float b = g_nv[(size_t)n * 48 + 16 + l];
            float c = g_nv[(size_t)n * 48 + 32 + l];
            snvn[grp][l] = sqrtf(a * a + b * b + c * c);
        }
        __syncthreads();

        if (tt < 16) {
            float acc = s_b1[tt];
            #pragma unroll
            for (int k = 0; k < 16; k++) acc += sacc[grp][k] * s_w1[k * 16 + tt];
            #pragma unroll
            for (int k = 0; k < 16; k++) acc += snvn[grp][k] * s_w1[(16 + k) * 16 + tt];
            sh[grp][tt] = siluf(acc);
        }
        __syncthreads();

        float nsu = s_b2[tt];
        #pragma unroll
        for (int l = 0; l < 16; l++) nsu += sh[grp][l] * s_w2[l * 128 + tt];
        float xv = nsu + node_s[(size_t)n * 128 + tt];

        float s1 = xv, s2 = xv * xv;
        #pragma unroll
        for (int o = 16; o > 0; o >>= 1) {
            s1 += __shfl_down_sync(0xffffffffu, s1, o);
            s2 += __shfl_down_sync(0xffffffffu, s2, o);
        }
        if ((tt & 31) == 0) { rs1[grp][tt >> 5] = s1; rs2[grp][tt >> 5] = s2; }
        __syncthreads();
        float ts1 = rs1[grp][0] + rs1[grp][1] + rs1[grp][2] + rs1[grp][3];
        float ts2 = rs2[grp][0] + rs2[grp][1] + rs2[grp][2] + rs2[grp][3];
        float mu = ts1 * (1.f / 128.f);
        float var = ts2 * (1.f / 128.f) - mu * mu;
        out[(size_t)n * 128 + tt] = (xv - mu) * rsqrtf(var + 1e-5f) * s_gam[tt] + s_bet[tt];

        float a0 = 0.f, a1 = 0.f, a2 = 0.f;
        #pragma unroll
        for (int l = 0; l < 16; l++) {
            float w = s_onw[l * 128 + tt];
            a0 += saccv[grp][l] * w;
            a1 += saccv[grp][16 + l] * w;
            a2 += saccv[grp][32 + l] * w;
        }
        float v0 = a0 + node_v[(size_t)n * 384 + tt];
        float v1 = a1 + node_v[(size_t)n * 384 + 128 + tt];
        float v2 = a2 + node_v[(size_t)n * 384 + 256 + tt];
        float vn = sqrtf(v0 * v0 + v1 * v1 + v2 * v2);
        float sc = s_cns[tt] / (vn + 1e-8f);
        size_t base = 6400000ull + (size_t)n * 384;
        out[base + tt]       = v0 * sc;
        out[base + 128 + tt] = v1 * sc;
        out[base + 256 + tt] = v2 * sc;
        __syncthreads();
    }
}

// ============================================================================
extern "C" void kernel_launch(void* const* d_in, const int* in_sizes, int n_in,
                              void* d_out, int out_size)
{
    const float* node_s  = (const float*)d_in[0];
    const float* node_v  = (const float*)d_in[1];
    const float* edge_s  = (const float*)d_in[2];
    const float* edge_v  = (const float*)d_in[3];
    const float* dist    = (const float*)d_in[4];
    const float* vctr    = (const float*)d_in[5];
    const int*   src     = (const int*)d_in[6];
    const int*   dst     = (const int*)d_in[7];
    const float* ns_in_w = (const float*)d_in[8];
    const float* ns_in_b = (const float*)d_in[9];
    const float* nv_in_w = (const float*)d_in[10];
    const float* en_w    = (const float*)d_in[11];
    const float* en_b    = (const float*)d_in[12];
    const float* tp_w    = (const float*)d_in[13];
    const float* tp_b    = (const float*)d_in[14];
    const float* gate_w1 = (const float*)d_in[15];
    const float* gate_b1 = (const float*)d_in[16];
    const float* gate_w2 = (const float*)d_in[17];
    const float* gate_b2 = (const float*)d_in[18];
    const float* tv_w    = (const float*)d_in[19];
    const float* tv_b    = (const float*)d_in[20];
    const float* out_nv_w= (const float*)d_in[21];
    const float* ons_w1  = (const float*)d_in[22];
    const float* ons_b1  = (const float*)d_in[23];
    const float* ons_w2  = (const float*)d_in[24];
    const float* ons_b2  = (const float*)d_in[25];
    const float* ln_gamma= (const float*)d_in[26];
    const float* ln_beta = (const float*)d_in[27];
    const float* cn_scale= (const float*)d_in[28];

    float* out = (float*)d_out;
    float* out_es = out + 25600000ull;
    float* out_ev = out + 51200000ull;

    k_node_in<<<1563, 256>>>(node_s, node_v, ns_in_w, ns_in_b, nv_in_w, en_w, en_b);
    k_edge<<<N_EDGES / 128, 128>>>(edge_s, edge_v, dist, vctr, src, dst,
                                   tp_w, tp_b, gate_w1, gate_b1, gate_w2, gate_b2,
                                   tv_w, tv_b, out_es, out_ev);
    k_node_out<<<N_NODES / K3_NPB, 256>>>(node_s, node_v, out_nv_w, ons_w1, ons_b1,
                                          ons_w2, ons_b2, ln_gamma, ln_beta, cn_scale, out);
}

// round 4
// speedup vs baseline: 1.1098x; 1.0703x over previous
#include <cuda_runtime.h>
#include <math.h>
#include <stdint.h>

#define N_NODES 50000
#define N_EDGES 1600000
#define G 128
#define LG 16
#define PI_F 3.14159265358979323846f

typedef unsigned long long u64;

// ---- scratch (device globals; no allocation allowed) ----
__device__ __align__(16) float g_a[N_NODES * LG];        // n_s @ en_w[0:16]
__device__ __align__(16) float g_b[N_NODES * LG];        // n_s @ en_w[16:32] + en_b
__device__ __align__(16) float g_nv[N_NODES * 3 * LG];   // node_v @ nv_in_w
__device__ __align__(16) float g_acc_s[N_NODES * LG];    // segment sums
__device__ __align__(16) float g_acc_v[N_NODES * 3 * LG];

__device__ __forceinline__ float siluf(float x) { return x / (1.f + __expf(-x)); }

__device__ __forceinline__ void red4(float* p, float a, float b, float c, float d) {
    asm volatile("red.global.add.v4.f32 [%0], {%1,%2,%3,%4};"
                 :: "l"(p), "f"(a), "f"(b), "f"(c), "f"(d) : "memory");
}

// ---- packed f32x2 helpers ----
__device__ __forceinline__ u64 ffma2(u64 a, u64 b, u64 c) {
    u64 d; asm("fma.rn.f32x2 %0,%1,%2,%3;" : "=l"(d) : "l"(a), "l"(b), "l"(c)); return d;
}
__device__ __forceinline__ u64 mul2(u64 a, u64 b) {
    u64 d; asm("mul.rn.f32x2 %0,%1,%2;" : "=l"(d) : "l"(a), "l"(b)); return d;
}
__device__ __forceinline__ u64 add2(u64 a, u64 b) {
    u64 d; asm("add.rn.f32x2 %0,%1,%2;" : "=l"(d) : "l"(a), "l"(b)); return d;
}
__device__ __forceinline__ u64 pk2(float x, float y) {
    u64 r; asm("mov.b64 %0,{%1,%2};" : "=l"(r) : "f"(x), "f"(y)); return r;
}
__device__ __forceinline__ float2 upk(u64 a) {
    float lo, hi; asm("mov.b64 {%0,%1},%2;" : "=f"(lo), "=f"(hi) : "l"(a));
    return make_float2(lo, hi);
}

// ============================================================================
// Kernel 1: node input projections. 592 blocks (one wave), weights persistent
// in SMEM, 256 thr = 16 j-lanes x 16 node slots. Multi-accumulator dots,
// weight LDS hoisted across the 3 vector components.
// ============================================================================
#define WPAD 130
#define K1_TILES (N_NODES / 16)   // 3125
#define K1_BLOCKS 592

__global__ void __launch_bounds__(256) k_node_in(
    const float* __restrict__ node_s, const float* __restrict__ node_v,
    const float* __restrict__ ns_w, const float* __restrict__ ns_b,
    const float* __restrict__ nv_w, const float* __restrict__ en_w,
    const float* __restrict__ en_b)
{
    __shared__ __align__(16) float s_wsT[16 * WPAD];
    __shared__ __align__(16) float s_wvT[16 * WPAD];
    __shared__ __align__(16) float s_en[512];
    __shared__ float s_sns[16 * 16];
    __shared__ float s_nsb[16], s_enb[16];

    int t = threadIdx.x;

    // zero segment-sum accumulators (grid-stride)
    {
        float4* as4 = (float4*)g_acc_s;   // 200000 float4
        float4* av4 = (float4*)g_acc_v;   // 600000 float4
        int idx = blockIdx.x * 256 + t;
        int stride = K1_BLOCKS * 256;
        for (int i = idx; i < 200000; i += stride) as4[i] = make_float4(0.f, 0.f, 0.f, 0.f);
        for (int i = idx; i < 600000; i += stride) av4[i] = make_float4(0.f, 0.f, 0.f, 0.f);
    }

    // weights -> SMEM once (transposed)
    for (int i = t; i < 2048; i += 256) {
        int gg = i >> 4, j = i & 15;
        s_wsT[j * WPAD + gg] = ns_w[i];
        s_wvT[j * WPAD + gg] = nv_w[i];
    }
    for (int i = t; i < 512; i += 256) s_en[i] = en_w[i];
    if (t < 16) { s_nsb[t] = ns_b[t]; s_enb[t] = en_b[t]; }
    __syncthreads();

    int j = t & 15, slot = t >> 4;
    const float2* w2s = (const float2*)(s_wsT + j * WPAD);
    const float2* w2v = (const float2*)(s_wvT + j * WPAD);

    for (int tile = blockIdx.x; tile < K1_TILES; tile += K1_BLOCKS) {
        int n = tile * 16 + slot;

        // scalar dot, 4 parallel accumulator chains
        {
            const float4* r4 = (const float4*)(node_s + (size_t)n * 128);
            float a0 = 0.f, a1 = 0.f, a2 = 0.f, a3 = 0.f;
            #pragma unroll 8
            for (int q = 0; q < 32; q++) {
                float4 r = __ldg(r4 + q);
                float2 wa = w2s[2 * q], wb = w2s[2 * q + 1];
                a0 += r.x * wa.x; a1 += r.y * wa.y; a2 += r.z * wb.x; a3 += r.w * wb.y;
            }
            s_sns[slot * 16 + j] = siluf((a0 + a1) + (a2 + a3) + s_nsb[j]);
        }

        // vector dots: weight LDS shared across x, 2 chains per component
        {
            const float4* v0 = (const float4*)(node_v + (size_t)n * 384);
            const float4* v1 = v0 + 32;
            const float4* v2 = v0 + 64;
            float a0a = 0.f, a0b = 0.f, a1a = 0.f, a1b = 0.f, a2a = 0.f, a2b = 0.f;
            #pragma unroll 8
            for (int q = 0; q < 32; q++) {
                float2 wa = w2v[2 * q], wb = w2v[2 * q + 1];
                float4 r0 = __ldg(v0 + q), r1 = __ldg(v1 + q), r2 = __ldg(v2 + q);
                a0a += r0.x * wa.x; a0b += r0.z * wb.x;
                a1a += r1.x * wa.x; a1b += r1.z * wb.x;
                a2a += r2.x * wa.x; a2b += r2.z * wb.x;
                a0a += r0.y * wa.y; a0b += r0.w * wb.y;
                a1a += r1.y * wa.y; a1b += r1.w * wb.y;
                a2a += r2.y * wa.y; a2b += r2.w * wb.y;
            }
            g_nv[(size_t)n * 48 + j]      = a0a + a0b;
            g_nv[(size_t)n * 48 + 16 + j] = a1a + a1b;
            g_nv[(size_t)n * 48 + 32 + j] = a2a + a2b;
        }
        __syncthreads();

        // en_w pre-split
        {
            float a = 0.f, b = s_enb[j];
            #pragma unroll
            for (int k = 0; k < 16; k++) {
                float x = s_sns[slot * 16 + k];
                a += x * s_en[k * 16 + j];
                b += x * s_en[(16 + k) * 16 + j];
            }
            g_a[(size_t)n * 16 + j] = a;
            g_b[(size_t)n * 16 + j] = b;
        }
        __syncthreads();
    }
}

// ============================================================================
// Kernel 2: per-edge fused chain, f32x2-packed, single packed representation,
// reg cap 128 (4 blocks/SM).
// ============================================================================
__global__ void __launch_bounds__(128, 4) k_edge(
    const float* __restrict__ edge_s, const float* __restrict__ edge_v,
    const float* __restrict__ dist,   const float* __restrict__ vctr,
    const int* __restrict__ src,      const int* __restrict__ dst,
    const float* __restrict__ tp_w, const float* __restrict__ tp_b,
    const float* __restrict__ g1w,  const float* __restrict__ g1b,
    const float* __restrict__ g2w,  const float* __restrict__ g2b,
    const float* __restrict__ tvw,  const float* __restrict__ tvb,
    float* __restrict__ out_es, float* __restrict__ out_ev)
{
    __shared__ __align__(16) float s_tp[256], s_g1[256], s_g2[256], s_tv[768];
    __shared__ __align__(16) float s_tpb[16], s_g1b[16], s_g2b[16], s_tvb[48];
    int t = threadIdx.x;
    for (int i = t; i < 256; i += 128) { s_tp[i] = tp_w[i]; s_g1[i] = g1w[i]; s_g2[i] = g2w[i]; }
    for (int i = t; i < 768; i += 128) s_tv[i] = tvw[i];
    if (t < 16) { s_tpb[t] = tp_b[t]; s_g1b[t] = g1b[t]; s_g2b[t] = g2b[t]; }
    if (t < 48) s_tvb[t] = tvb[t];
    __syncthreads();

    int e = blockIdx.x * 128 + t;
    int s = src[e], d = dst[e];
    float dd = __ldg(dist + e);

    // gather a[src]+b[dst], packed
    u64 en2[8];
    {
        const ulonglong2* pa = (const ulonglong2*)(g_a + (size_t)s * 16);
        const ulonglong2* pb = (const ulonglong2*)(g_b + (size_t)d * 16);
        #pragma unroll
        for (int i = 0; i < 4; i++) {
            ulonglong2 va = __ldg(pa + i), vb = __ldg(pb + i);
            en2[2 * i] = add2(va.x, vb.x);
            en2[2 * i + 1] = add2(va.y, vb.y);
        }
    }

    // edge_s row, packed
    u64 esl2[8];
    {
        const ulonglong2* p = (const ulonglong2*)(edge_s + (size_t)e * 16);
        #pragma unroll
        for (int i = 0; i < 4; i++) {
            ulonglong2 v = __ldg(p + i);
            esl2[2 * i] = v.x; esl2[2 * i + 1] = v.y;
        }
    }

    // tm = en * (edge_s @ tp_w + tp_b)
    u64 tm2[8];
    {
        const ulonglong2* bb = (const ulonglong2*)s_tpb;
        #pragma unroll
        for (int i = 0; i < 4; i++) { ulonglong2 v = bb[i]; tm2[2 * i] = v.x; tm2[2 * i + 1] = v.y; }
    }
    #pragma unroll
    for (int p = 0; p < 8; p++) {
        float2 xv = upk(esl2[p]);
        {
            u64 xx = pk2(xv.x, xv.x);
            const ulonglong2* w = (const ulonglong2*)(s_tp + (2 * p) * 16);
            #pragma unroll
            for (int i = 0; i < 4; i++) {
                ulonglong2 wv = w[i];
                tm2[2 * i]     = ffma2(xx, wv.x, tm2[2 * i]);
                tm2[2 * i + 1] = ffma2(xx, wv.y, tm2[2 * i + 1]);
            }
        }
        {
            u64 xx = pk2(xv.y, xv.y);
            const ulonglong2* w = (const ulonglong2*)(s_tp + (2 * p + 1) * 16);
            #pragma unroll
            for (int i = 0; i < 4; i++) {
                ulonglong2 wv = w[i];
                tm2[2 * i]     = ffma2(xx, wv.x, tm2[2 * i]);
                tm2[2 * i + 1] = ffma2(xx, wv.y, tm2[2 * i + 1]);
            }
        }
    }
    #pragma unroll
    for (int i = 0; i < 8; i++) tm2[i] = mul2(tm2[i], en2[i]);

    // h = silu(tm @ g1 + b1)
    u64 h2[8];
    {
        const ulonglong2* bb = (const ulonglong2*)s_g1b;
        #pragma unroll
        for (int i = 0; i < 4; i++) { ulonglong2 v = bb[i]; h2[2 * i] = v.x; h2[2 * i + 1] = v.y; }
    }
    #pragma unroll
    for (int p = 0; p < 8; p++) {
        float2 xv = upk(tm2[p]);
        {
            u64 xx = pk2(xv.x, xv.x);
            const ulonglong2* w = (const ulonglong2*)(s_g1 + (2 * p) * 16);
            #pragma unroll
            for (int i = 0; i < 4; i++) {
                ulonglong2 wv = w[i];
                h2[2 * i]     = ffma2(xx, wv.x, h2[2 * i]);
                h2[2 * i + 1] = ffma2(xx, wv.y, h2[2 * i + 1]);
            }
        }
        {
            u64 xx = pk2(xv.y, xv.y);
            const ulonglong2* w = (const ulonglong2*)(s_g1 + (2 * p + 1) * 16);
            #pragma unroll
            for (int i = 0; i < 4; i++) {
                ulonglong2 wv = w[i];
                h2[2 * i]     = ffma2(xx, wv.x, h2[2 * i]);
                h2[2 * i + 1] = ffma2(xx, wv.y, h2[2 * i + 1]);
            }
        }
    }
    #pragma unroll
    for (int i = 0; i < 8; i++) {
        float2 v = upk(h2[i]);
        h2[i] = pk2(siluf(v.x), siluf(v.y));
    }

    // gt = h @ g2 + b2
    u64 gt2[8];
    {
        const ulonglong2* bb = (const ulonglong2*)s_g2b;
        #pragma unroll
        for (int i = 0; i < 4; i++) { ulonglong2 v = bb[i]; gt2[2 * i] = v.x; gt2[2 * i + 1] = v.y; }
    }
    #pragma unroll
    for (int p = 0; p < 8; p++) {
        float2 xv = upk(h2[p]);
        {
            u64 xx = pk2(xv.x, xv.x);
            const ulonglong2* w = (const ulonglong2*)(s_g2 + (2 * p) * 16);
            #pragma unroll
            for (int i = 0; i < 4; i++) {
                ulonglong2 wv = w[i];
                gt2[2 * i]     = ffma2(xx, wv.x, gt2[2 * i]);
                gt2[2 * i + 1] = ffma2(xx, wv.y, gt2[2 * i + 1]);
            }
        }
        {
            u64 xx = pk2(xv.y, xv.y);
            const ulonglong2* w = (const ulonglong2*)(s_g2 + (2 * p + 1) * 16);
            #pragma unroll
            for (int i = 0; i < 4; i++) {
                ulonglong2 wv = w[i];
                gt2[2 * i]     = ffma2(xx, wv.x, gt2[2 * i]);
                gt2[2 * i + 1] = ffma2(xx, wv.y, gt2[2 * i + 1]);
            }
        }
    }

    float C = 0.5f * (__cosf(PI_F * dd * 0.1f) + 1.f) * (dd < 10.f ? 1.f : 0.f);

    // es = tm * sigmoid(gt) * C  (scalar form; tm2/gt2 die here)
    float es[16];
    #pragma unroll
    for (int i = 0; i < 8; i++) {
        float2 tv = upk(tm2[i]);
        float2 gv = upk(gt2[i]);
        es[2 * i]     = tv.x * (1.f / (1.f + __expf(-gv.x))) * C;
        es[2 * i + 1] = tv.y * (1.f / (1.f + __expf(-gv.y))) * C;
    }

    // edge_s_out + scatter
    {
        float4* po = (float4*)(out_es + (size_t)e * 16);
        #pragma unroll
        for (int i = 0; i < 4; i++) {
            float2 a = upk(esl2[2 * i]), b = upk(esl2[2 * i + 1]);
            float4 v;
            v.x = es[4 * i]     + a.x;
            v.y = es[4 * i + 1] + a.y;
            v.z = es[4 * i + 2] + b.x;
            v.w = es[4 * i + 3] + b.y;
            po[i] = v;
        }
        float* pacc = g_acc_s + (size_t)d * 16;
        #pragma unroll
        for (int i = 0; i < 4; i++)
            red4(pacc + 4 * i, es[4 * i], es[4 * i + 1], es[4 * i + 2], es[4 * i + 3]);
    }

    // ter = (es @ tv_w + tv_b) * C   (24 packed pairs: [t|e|r])
    u64 ter2[24];
    {
        const ulonglong2* bb = (const ulonglong2*)s_tvb;
        #pragma unroll
        for (int i = 0; i < 12; i++) { ulonglong2 v = bb[i]; ter2[2 * i] = v.x; ter2[2 * i + 1] = v.y; }
    }
    #pragma unroll
    for (int k = 0; k < 16; k++) {
        u64 xx = pk2(es[k], es[k]);
        const ulonglong2* w = (const ulonglong2*)(s_tv + k * 48);
        #pragma unroll
        for (int i = 0; i < 12; i++) {
            ulonglong2 wv = w[i];
            ter2[2 * i]     = ffma2(xx, wv.x, ter2[2 * i]);
            ter2[2 * i + 1] = ffma2(xx, wv.y, ter2[2 * i + 1]);
        }
    }
    {
        u64 CC = pk2(C, C);
        #pragma unroll
        for (int i = 0; i < 24; i++) ter2[i] = mul2(ter2[i], CC);
    }

    float vn0 = __ldg(vctr + (size_t)e * 3);
    float vn1 = __ldg(vctr + (size_t)e * 3 + 1);
    float vn2 = __ldg(vctr + (size_t)e * 3 + 2);

    #pragma unroll
    for (int x = 0; x < 3; x++) {
        float vnx = (x == 0) ? vn0 : (x == 1) ? vn1 : vn2;
        u64 vnxx = pk2(vnx, vnx);
        const ulonglong2* pe = (const ulonglong2*)(edge_v + (size_t)e * 48 + x * 16);
        const ulonglong2* pn = (const ulonglong2*)(g_nv + (size_t)s * 48 + x * 16);
        u64 evi[8], nvs[8];
        #pragma unroll
        for (int i = 0; i < 4; i++) {
            ulonglong2 a = __ldg(pe + i);
            ulonglong2 b = __ldg(pn + i);
            evi[2 * i] = a.x; evi[2 * i + 1] = a.y;
            nvs[2 * i] = b.x; nvs[2 * i + 1] = b.y;
        }
        u64 evu[8];
        #pragma unroll
        for (int i = 0; i < 8; i++)
            evu[i] = ffma2(evi[i], ter2[i], ffma2(nvs[i], ter2[8 + i], mul2(vnxx, ter2[16 + i])));

        ulonglong2* po = (ulonglong2*)(out_ev + (size_t)e * 48 + x * 16);
        #pragma unroll
        for (int i = 0; i < 4; i++) {
            ulonglong2 o;
            o.x = add2(evu[2 * i], evi[2 * i]);
            o.y = add2(evu[2 * i + 1], evi[2 * i + 1]);
            po[i] = o;
        }
        float* pacc = g_acc_v + (size_t)d * 48 + x * 16;
        #pragma unroll
        for (int i = 0; i < 4; i++) {
            float2 a = upk(evu[2 * i]);
            float2 b = upk(evu[2 * i + 1]);
            red4(pacc + 4 * i, a.x, a.y, b.x, b.y);
        }
    }
}

// ============================================================================
// Kernel 3: node epilogue. 256 threads = 2 nodes in parallel; weights in SMEM.
// ============================================================================
#define K3_NPB 16
__global__ void __launch_bounds__(256) k_node_out(
    const float* __restrict__ node_s, const float* __restrict__ node_v,
    const float* __restrict__ onw,
    const float* __restrict__ w1, const float* __restrict__ b1,
    const float* __restrict__ w2, const float* __restrict__ b2,
    const float* __restrict__ gamma, const float* __restrict__ beta,
    const float* __restrict__ cns, float* __restrict__ out)
{
    __shared__ __align__(16) float s_w1[512], s_w2[2048], s_onw[2048];
    __shared__ float s_b1[16], s_b2[128], s_gam[128], s_bet[128], s_cns[128];
    __shared__ float sacc[2][16], snvn[2][16], sh[2][16], saccv[2][48];
    __shared__ float rs1[2][4], rs2[2][4];

    int t = threadIdx.x;
    for (int i = t; i < 512; i += 256) s_w1[i] = w1[i];
    for (int i = t; i < 2048; i += 256) { s_w2[i] = w2[i]; s_onw[i] = onw[i]; }
    if (t < 16) s_b1[t] = b1[t];
    if (t < 128) { s_b2[t] = b2[t]; s_gam[t] = gamma[t]; s_bet[t] = beta[t]; s_cns[t] = cns[t]; }
    __syncthreads();

    int grp = t >> 7, tt = t & 127;
    int n0 = blockIdx.x * K3_NPB;

    for (int it = 0; it < K3_NPB; it += 2) {
        int n = n0 + it + grp;

        if (tt < 16) sacc[grp][tt] = g_acc_s[(size_t)n * 16 + tt];
        else if (tt < 64) saccv[grp][tt - 16] = g_acc_v[(size_t)n * 48 + (tt - 16)];
        else if (tt < 80) {
            int l = tt - 64;
            float a = g_nv[(size_t)n * 48 + l];
            float b = g_nv[(size_t)n * 48 + 16 + l];
            float c = g_nv[(size_t)n * 48 + 32 + l];
            snvn[grp][l] = sqrtf(a * a + b * b + c * c);
        }
        __syncthreads();

        if (tt < 16) {
            float acc = s_b1[tt];
            #pragma unroll
            for (int k = 0; k < 16; k++) acc += sacc[grp][k] * s_w1[k * 16 + tt];
            #pragma unroll
            for (int k = 0; k < 16; k++) acc += snvn[grp][k] * s_w1[(16 + k) * 16 + tt];
            sh[grp][tt] = siluf(acc);
        }
        __syncthreads();

        float nsu = s_b2[tt];
        #pragma unroll
        for (int l = 0; l < 16; l++) nsu += sh[grp][l] * s_w2[l * 128 + tt];
        float xv = nsu + node_s[(size_t)n * 128 + tt];

        float s1 = xv, s2 = xv * xv;
        #pragma unroll
        for (int o = 16; o > 0; o >>= 1) {
            s1 += __shfl_down_sync(0xffffffffu, s1, o);
            s2 += __shfl_down_sync(0xffffffffu, s2, o);
        }
        if ((tt & 31) == 0) { rs1[grp][tt >> 5] = s1; rs2[grp][tt >> 5] = s2; }
        __syncthreads();
        float ts1 = rs1[grp][0] + rs1[grp][1] + rs1[grp][2] + rs1[grp][3];
        float ts2 = rs2[grp][0] + rs2[grp][1] + rs2[grp][2] + rs2[grp][3];
        float mu = ts1 * (1.f / 128.f);
        float var = ts2 * (1.f / 128.f) - mu * mu;
        out[(size_t)n * 128 + tt] = (xv - mu) * rsqrtf(var + 1e-5f) * s_gam[tt] + s_bet[tt];

        float a0 = 0.f, a1 = 0.f, a2 = 0.f;
        #pragma unroll
        for (int l = 0; l < 16; l++) {
            float w = s_onw[l * 128 + tt];
            a0 += saccv[grp][l] * w;
            a1 += saccv[grp][16 + l] * w;
            a2 += saccv[grp][32 + l] * w;
        }
        float v0 = a0 + node_v[(size_t)n * 384 + tt];
        float v1 = a1 + node_v[(size_t)n * 384 + 128 + tt];
        float v2 = a2 + node_v[(size_t)n * 384 + 256 + tt];
        float vn = sqrtf(v0 * v0 + v1 * v1 + v2 * v2);
        float sc = s_cns[tt] / (vn + 1e-8f);
        size_t base = 6400000ull + (size_t)n * 384;
        out[base + tt]       = v0 * sc;
        out[base + 128 + tt] = v1 * sc;
        out[base + 256 + tt] = v2 * sc;
        __syncthreads();
    }
}

// ============================================================================
extern "C" void kernel_launch(void* const* d_in, const int* in_sizes, int n_in,
                              void* d_out, int out_size)
{
    const float* node_s  = (const float*)d_in[0];
    const float* node_v  = (const float*)d_in[1];
    const float* edge_s  = (const float*)d_in[2];
    const float* edge_v  = (const float*)d_in[3];
    const float* dist    = (const float*)d_in[4];
    const float* vctr    = (const float*)d_in[5];
    const int*   src     = (const int*)d_in[6];
    const int*   dst     = (const int*)d_in[7];
    const float* ns_in_w = (const float*)d_in[8];
    const float* ns_in_b = (const float*)d_in[9];
    const float* nv_in_w = (const float*)d_in[10];
    const float* en_w    = (const float*)d_in[11];
    const float* en_b    = (const float*)d_in[12];
    const float* tp_w    = (const float*)d_in[13];
    const float* tp_b    = (const float*)d_in[14];
    const float* gate_w1 = (const float*)d_in[15];
    const float* gate_b1 = (const float*)d_in[16];
    const float* gate_w2 = (const float*)d_in[17];
    const float* gate_b2 = (const float*)d_in[18];
    const float* tv_w    = (const float*)d_in[19];
    const float* tv_b    = (const float*)d_in[20];
    const float* out_nv_w= (const float*)d_in[21];
    const float* ons_w1  = (const float*)d_in[22];
    const float* ons_b1  = (const float*)d_in[23];
    const float* ons_w2  = (const float*)d_in[24];
    const float* ons_b2  = (const float*)d_in[25];
    const float* ln_gamma= (const float*)d_in[26];
    const float* ln_beta = (const float*)d_in[27];
    const float* cn_scale= (const float*)d_in[28];

    float* out = (float*)d_out;
    float* out_es = out + 25600000ull;
    float* out_ev = out + 51200000ull;

    k_node_in<<<K1_BLOCKS, 256>>>(node_s, node_v, ns_in_w, ns_in_b, nv_in_w, en_w, en_b);
    k_edge<<<N_EDGES / 128, 128>>>(edge_s, edge_v, dist, vctr, src, dst,
                                   tp_w, tp_b, gate_w1, gate_b1, gate_w2, gate_b2,
                                   tv_w, tv_b, out_es, out_ev);
    k_node_out<<<N_NODES / K3_NPB, 256>>>(node_s, node_v, out_nv_w, ons_w1, ons_b1,
                                          ons_w2, ons_b2, ln_gamma, ln_beta, cn_scale, out);
}

// round 5
// speedup vs baseline: 1.2539x; 1.1299x over previous
#include <cuda_runtime.h>
#include <math.h>
#include <stdint.h>

#define N_NODES 50000
#define N_EDGES 1600000
#define G 128
#define LG 16
#define PI_F 3.14159265358979323846f

typedef unsigned long long u64;

// ---- scratch (device globals; no allocation allowed) ----
__device__ __align__(16) float g_a[N_NODES * LG];
__device__ __align__(16) float g_b[N_NODES * LG];
__device__ __align__(16) float g_nv[N_NODES * 3 * LG];
__device__ __align__(16) float g_acc_s[N_NODES * LG];
__device__ __align__(16) float g_acc_v[N_NODES * 3 * LG];

__device__ __forceinline__ float siluf(float x) { return x / (1.f + __expf(-x)); }

__device__ __forceinline__ void red4(float* p, float a, float b, float c, float d) {
    asm volatile("red.global.add.v4.f32 [%0], {%1,%2,%3,%4};"
                 :: "l"(p), "f"(a), "f"(b), "f"(c), "f"(d) : "memory");
}

// ---- packed f32x2 helpers ----
__device__ __forceinline__ u64 ffma2(u64 a, u64 b, u64 c) {
    u64 d; asm("fma.rn.f32x2 %0,%1,%2,%3;" : "=l"(d) : "l"(a), "l"(b), "l"(c)); return d;
}
__device__ __forceinline__ u64 mul2(u64 a, u64 b) {
    u64 d; asm("mul.rn.f32x2 %0,%1,%2;" : "=l"(d) : "l"(a), "l"(b)); return d;
}
__device__ __forceinline__ u64 add2(u64 a, u64 b) {
    u64 d; asm("add.rn.f32x2 %0,%1,%2;" : "=l"(d) : "l"(a), "l"(b)); return d;
}
__device__ __forceinline__ u64 pk2(float x, float y) {
    u64 r; asm("mov.b64 %0,{%1,%2};" : "=l"(r) : "f"(x), "f"(y)); return r;
}
__device__ __forceinline__ float2 upk(u64 a) {
    float lo, hi; asm("mov.b64 {%0,%1},%2;" : "=f"(lo), "=f"(hi) : "l"(a));
    return make_float2(lo, hi);
}

// ============================================================================
// Kernel 1: node input projections (unchanged from R4 — 87us, known good)
// ============================================================================
#define WPAD 130
#define K1_TILES (N_NODES / 16)
#define K1_BLOCKS 592

__global__ void __launch_bounds__(256) k_node_in(
    const float* __restrict__ node_s, const float* __restrict__ node_v,
    const float* __restrict__ ns_w, const float* __restrict__ ns_b,
    const float* __restrict__ nv_w, const float* __restrict__ en_w,
    const float* __restrict__ en_b)
{
    __shared__ __align__(16) float s_wsT[16 * WPAD];
    __shared__ __align__(16) float s_wvT[16 * WPAD];
    __shared__ __align__(16) float s_en[512];
    __shared__ float s_sns[16 * 16];
    __shared__ float s_nsb[16], s_enb[16];

    int t = threadIdx.x;

    {
        float4* as4 = (float4*)g_acc_s;
        float4* av4 = (float4*)g_acc_v;
        int idx = blockIdx.x * 256 + t;
        int stride = K1_BLOCKS * 256;
        for (int i = idx; i < 200000; i += stride) as4[i] = make_float4(0.f, 0.f, 0.f, 0.f);
        for (int i = idx; i < 600000; i += stride) av4[i] = make_float4(0.f, 0.f, 0.f, 0.f);
    }

    for (int i = t; i < 2048; i += 256) {
        int gg = i >> 4, j = i & 15;
        s_wsT[j * WPAD + gg] = ns_w[i];
        s_wvT[j * WPAD + gg] = nv_w[i];
    }
    for (int i = t; i < 512; i += 256) s_en[i] = en_w[i];
    if (t < 16) { s_nsb[t] = ns_b[t]; s_enb[t] = en_b[t]; }
    __syncthreads();

    int j = t & 15, slot = t >> 4;
    const float2* w2s = (const float2*)(s_wsT + j * WPAD);
    const float2* w2v = (const float2*)(s_wvT + j * WPAD);

    for (int tile = blockIdx.x; tile < K1_TILES; tile += K1_BLOCKS) {
        int n = tile * 16 + slot;

        {
            const float4* r4 = (const float4*)(node_s + (size_t)n * 128);
            float a0 = 0.f, a1 = 0.f, a2 = 0.f, a3 = 0.f;
            #pragma unroll 8
            for (int q = 0; q < 32; q++) {
                float4 r = __ldg(r4 + q);
                float2 wa = w2s[2 * q], wb = w2s[2 * q + 1];
                a0 += r.x * wa.x; a1 += r.y * wa.y; a2 += r.z * wb.x; a3 += r.w * wb.y;
            }
            s_sns[slot * 16 + j] = siluf((a0 + a1) + (a2 + a3) + s_nsb[j]);
        }

        {
            const float4* v0 = (const float4*)(node_v + (size_t)n * 384);
            const float4* v1 = v0 + 32;
            const float4* v2 = v0 + 64;
            float a0a = 0.f, a0b = 0.f, a1a = 0.f, a1b = 0.f, a2a = 0.f, a2b = 0.f;
            #pragma unroll 8
            for (int q = 0; q < 32; q++) {
                float2 wa = w2v[2 * q], wb = w2v[2 * q + 1];
                float4 r0 = __ldg(v0 + q), r1 = __ldg(v1 + q), r2 = __ldg(v2 + q);
                a0a += r0.x * wa.x; a0b += r0.z * wb.x;
                a1a += r1.x * wa.x; a1b += r1.z * wb.x;
                a2a += r2.x * wa.x; a2b += r2.z * wb.x;
                a0a += r0.y * wa.y; a0b += r0.w * wb.y;
                a1a += r1.y * wa.y; a1b += r1.w * wb.y;
                a2a += r2.y * wa.y; a2b += r2.w * wb.y;
            }
            g_nv[(size_t)n * 48 + j]      = a0a + a0b;
            g_nv[(size_t)n * 48 + 16 + j] = a1a + a1b;
            g_nv[(size_t)n * 48 + 32 + j] = a2a + a2b;
        }
        __syncthreads();

        {
            float a = 0.f, b = s_enb[j];
            #pragma unroll
            for (int k = 0; k < 16; k++) {
                float x = s_sns[slot * 16 + k];
                a += x * s_en[k * 16 + j];
                b += x * s_en[(16 + k) * 16 + j];
            }
            g_a[(size_t)n * 16 + j] = a;
            g_b[(size_t)n * 16 + j] = b;
        }
        __syncthreads();
    }
}

// ============================================================================
// Kernel 2: QUAD layout — 4 lanes per edge, lane q owns channels 4q..4q+3
// (2 packed f32x2 regs/stage). Inputs broadcast via quad shuffles.
// Low regs -> high occupancy; all edge streams fully coalesced.
// ============================================================================

// y0,y1 (packed pair, lane's 4 channels) += sum_k x[k] * W[k][4q..4q+3]
// X0,X1: this lane's packed pair holding channels 4q..4q+3 of the input vec.
#define MATVEC16x4(Y0, Y1, X0, X1, SW, Q)                                    \
    {                                                                        \
        _Pragma("unroll")                                                    \
        for (int k = 0; k < 16; k++) {                                       \
            float2 xp = upk(((k & 2) ? (X1) : (X0)));                        \
            float xs = (k & 1) ? xp.y : xp.x;                                \
            float xk = __shfl_sync(0xffffffffu, xs, k >> 2, 4);              \
            u64 xx = pk2(xk, xk);                                            \
            ulonglong2 w = ((const ulonglong2*)((SW) + k * 16))[Q];          \
            (Y0) = ffma2(xx, w.x, (Y0));                                     \
            (Y1) = ffma2(xx, w.y, (Y1));                                     \
        }                                                                    \
    }

__global__ void __launch_bounds__(256) k_edge(
    const float* __restrict__ edge_s, const float* __restrict__ edge_v,
    const float* __restrict__ dist,   const float* __restrict__ vctr,
    const int* __restrict__ src,      const int* __restrict__ dst,
    const float* __restrict__ tp_w, const float* __restrict__ tp_b,
    const float* __restrict__ g1w,  const float* __restrict__ g1b,
    const float* __restrict__ g2w,  const float* __restrict__ g2b,
    const float* __restrict__ tvw,  const float* __restrict__ tvb,
    float* __restrict__ out_es, float* __restrict__ out_ev)
{
    __shared__ __align__(16) float s_tp[256], s_g1[256], s_g2[256], s_tv[768];
    __shared__ __align__(16) float s_tpb[16], s_g1b[16], s_g2b[16], s_tvb[48];
    int t = threadIdx.x;
    for (int i = t; i < 256; i += 256) { s_tp[i] = tp_w[i]; s_g1[i] = g1w[i]; s_g2[i] = g2w[i]; }
    for (int i = t; i < 768; i += 256) s_tv[i] = tvw[i];
    if (t < 16) { s_tpb[t] = tp_b[t]; s_g1b[t] = g1b[t]; s_g2b[t] = g2b[t]; }
    if (t < 48) s_tvb[t] = tvb[t];
    __syncthreads();

    int q = t & 3;
    int e = blockIdx.x * 64 + (t >> 2);

    int s = src[e], d = dst[e];
    float dd = dist[e];

    // this lane's 4 channels of edge_s (coalesced 64B/edge across quad)
    u64 esl0, esl1;
    {
        ulonglong2 v = ((const ulonglong2*)edge_s)[(size_t)e * 4 + q];
        esl0 = v.x; esl1 = v.y;
    }

    // gather a[src]+b[dst] for this lane's channels
    u64 en0, en1;
    {
        ulonglong2 va = __ldg((const ulonglong2*)g_a + (size_t)s * 4 + q);
        ulonglong2 vb = __ldg((const ulonglong2*)g_b + (size_t)d * 4 + q);
        en0 = add2(va.x, vb.x); en1 = add2(va.y, vb.y);
    }

    // tm = en * (edge_s @ tp_w + tp_b)
    u64 tm0, tm1;
    { ulonglong2 b = ((const ulonglong2*)s_tpb)[q]; tm0 = b.x; tm1 = b.y; }
    MATVEC16x4(tm0, tm1, esl0, esl1, s_tp, q);
    tm0 = mul2(tm0, en0); tm1 = mul2(tm1, en1);

    // h = silu(tm @ g1 + b1)
    u64 h0, h1;
    { ulonglong2 b = ((const ulonglong2*)s_g1b)[q]; h0 = b.x; h1 = b.y; }
    MATVEC16x4(h0, h1, tm0, tm1, s_g1, q);
    {
        float2 a = upk(h0), b = upk(h1);
        h0 = pk2(siluf(a.x), siluf(a.y));
        h1 = pk2(siluf(b.x), siluf(b.y));
    }

    // gt = h @ g2 + b2
    u64 gt0, gt1;
    { ulonglong2 b = ((const ulonglong2*)s_g2b)[q]; gt0 = b.x; gt1 = b.y; }
    MATVEC16x4(gt0, gt1, h0, h1, s_g2, q);

    float C = 0.5f * (__cosf(PI_F * dd * 0.1f) + 1.f) * (dd < 10.f ? 1.f : 0.f);

    // es = tm * sigmoid(gt) * C  (packed pair)
    u64 es0, es1;
    {
        float2 tv0 = upk(tm0), tv1 = upk(tm1);
        float2 gv0 = upk(gt0), gv1 = upk(gt1);
        es0 = pk2(tv0.x * (1.f / (1.f + __expf(-gv0.x))) * C,
                  tv0.y * (1.f / (1.f + __expf(-gv0.y))) * C);
        es1 = pk2(tv1.x * (1.f / (1.f + __expf(-gv1.x))) * C,
                  tv1.y * (1.f / (1.f + __expf(-gv1.y))) * C);
    }

    // edge_s_out + scatter (both coalesced per quad)
    {
        ulonglong2 o;
        o.x = add2(es0, esl0);
        o.y = add2(es1, esl1);
        ((ulonglong2*)out_es)[(size_t)e * 4 + q] = o;
        float2 a = upk(es0), b = upk(es1);
        red4(g_acc_s + (size_t)d * 16 + q * 4, a.x, a.y, b.x, b.y);
    }

    // ter = (es @ tv_w + tv_b) * C : lane holds its 4 channels of t/e/r
    u64 tt0, tt1, te0, te1, tr0, tr1;
    {
        ulonglong2 bt = ((const ulonglong2*)(s_tvb))[q];
        ulonglong2 be = ((const ulonglong2*)(s_tvb + 16))[q];
        ulonglong2 br = ((const ulonglong2*)(s_tvb + 32))[q];
        tt0 = bt.x; tt1 = bt.y; te0 = be.x; te1 = be.y; tr0 = br.x; tr1 = br.y;
    }
    #pragma unroll
    for (int k = 0; k < 16; k++) {
        float2 xp = upk((k & 2) ? es1 : es0);
        float xs = (k & 1) ? xp.y : xp.x;
        float xk = __shfl_sync(0xffffffffu, xs, k >> 2, 4);
        u64 xx = pk2(xk, xk);
        ulonglong2 wt = ((const ulonglong2*)(s_tv + k * 48))[q];
        ulonglong2 we = ((const ulonglong2*)(s_tv + k * 48 + 16))[q];
        ulonglong2 wr = ((const ulonglong2*)(s_tv + k * 48 + 32))[q];
        tt0 = ffma2(xx, wt.x, tt0); tt1 = ffma2(xx, wt.y, tt1);
        te0 = ffma2(xx, we.x, te0); te1 = ffma2(xx, we.y, te1);
        tr0 = ffma2(xx, wr.x, tr0); tr1 = ffma2(xx, wr.y, tr1);
    }
    {
        u64 CC = pk2(C, C);
        tt0 = mul2(tt0, CC); tt1 = mul2(tt1, CC);
        te0 = mul2(te0, CC); te1 = mul2(te1, CC);
        tr0 = mul2(tr0, CC); tr1 = mul2(tr1, CC);
    }

    float vn0 = vctr[(size_t)e * 3];
    float vn1 = vctr[(size_t)e * 3 + 1];
    float vn2 = vctr[(size_t)e * 3 + 2];

    #pragma unroll
    for (int x = 0; x < 3; x++) {
        float vnx = (x == 0) ? vn0 : (x == 1) ? vn1 : vn2;
        u64 vnxx = pk2(vnx, vnx);
        ulonglong2 evi = ((const ulonglong2*)(edge_v + (size_t)e * 48 + x * 16))[q];
        ulonglong2 nvs = __ldg((const ulonglong2*)(g_nv + (size_t)s * 48 + x * 16) + q);
        u64 evu0 = ffma2(evi.x, tt0, ffma2(nvs.x, te0, mul2(vnxx, tr0)));
        u64 evu1 = ffma2(evi.y, tt1, ffma2(nvs.y, te1, mul2(vnxx, tr1)));

        ulonglong2 o;
        o.x = add2(evu0, evi.x);
        o.y = add2(evu1, evi.y);
        ((ulonglong2*)(out_ev + (size_t)e * 48 + x * 16))[q] = o;

        float2 a = upk(evu0), b = upk(evu1);
        red4(g_acc_v + (size_t)d * 48 + x * 16 + q * 4, a.x, a.y, b.x, b.y);
    }
}

// ============================================================================
// Kernel 3: node epilogue (unchanged from R4)
// ============================================================================
#define K3_NPB 16
__global__ void __launch_bounds__(256) k_node_out(
    const float* __restrict__ node_s, const float* __restrict__ node_v,
    const float* __restrict__ onw,
    const float* __restrict__ w1, const float* __restrict__ b1,
    const float* __restrict__ w2, const float* __restrict__ b2,
    const float* __restrict__ gamma, const float* __restrict__ beta,
    const float* __restrict__ cns, float* __restrict__ out)
{
    __shared__ __align__(16) float s_w1[512], s_w2[2048], s_onw[2048];
    __shared__ float s_b1[16], s_b2[128], s_gam[128], s_bet[128], s_cns[128];
    __shared__ float sacc[2][16], snvn[2][16], sh[2][16], saccv[2][48];
    __shared__ float rs1[2][4], rs2[2][4];

    int t = threadIdx.x;
    for (int i = t; i < 512; i += 256) s_w1[i] = w1[i];
    for (int i = t; i < 2048; i += 256) { s_w2[i] = w2[i]; s_onw[i] = onw[i]; }
    if (t < 16) s_b1[t] = b1[t];
    if (t < 128) { s_b2[t] = b2[t]; s_gam[t] = gamma[t]; s_bet[t] = beta[t]; s_cns[t] = cns[t]; }
    __syncthreads();

    int grp = t >> 7, tt = t & 127;
    int n0 = blockIdx.x * K3_NPB;

    for (int it = 0; it < K3_NPB; it += 2) {
        int n = n0 + it + grp;

        if (tt < 16) sacc[grp][tt] = g_acc_s[(size_t)n * 16 + tt];
        else if (tt < 64) saccv[grp][tt - 16] = g_acc_v[(size_t)n * 48 + (tt - 16)];
        else if (tt < 80) {
            int l = tt - 64;
            float a = g_nv[(size_t)n * 48 + l];
            float b = g_nv[(size_t)n * 48 + 16 + l];
            float c = g_nv[(size_t)n * 48 + 32 + l];
            snvn[grp][l] = sqrtf(a * a + b * b + c * c);
        }
        __syncthreads();

        if (tt < 16) {
            float acc = s_b1[tt];
            #pragma unroll
            for (int k = 0; k < 16; k++) acc += sacc[grp][k] * s_w1[k * 16 + tt];
            #pragma unroll
            for (int k = 0; k < 16; k++) acc += snvn[grp][k] * s_w1[(16 + k) * 16 + tt];
            sh[grp][tt] = siluf(acc);
        }
        __syncthreads();

        float nsu = s_b2[tt];
        #pragma unroll
        for (int l = 0; l < 16; l++) nsu += sh[grp][l] * s_w2[l * 128 + tt];
        float xv = nsu + node_s[(size_t)n * 128 + tt];

        float s1 = xv, s2 = xv * xv;
        #pragma unroll
        for (int o = 16; o > 0; o >>= 1) {
            s1 += __shfl_down_sync(0xffffffffu, s1, o);
            s2 += __shfl_down_sync(0xffffffffu, s2, o);
        }
        if ((tt & 31) == 0) { rs1[grp][tt >> 5] = s1; rs2[grp][tt >> 5] = s2; }
        __syncthreads();
        float ts1 = rs1[grp][0] + rs1[grp][1] + rs1[grp][2] + rs1[grp][3];
        float ts2 = rs2[grp][0] + rs2[grp][1] + rs2[grp][2] + rs2[grp][3];
        float mu = ts1 * (1.f / 128.f);
        float var = ts2 * (1.f / 128.f) - mu * mu;
        out[(size_t)n * 128 + tt] = (xv - mu) * rsqrtf(var + 1e-5f) * s_gam[tt] + s_bet[tt];

        float a0 = 0.f, a1 = 0.f, a2 = 0.f;
        #pragma unroll
        for (int l = 0; l < 16; l++) {
            float w = s_onw[l * 128 + tt];
            a0 += saccv[grp][l] * w;
            a1 += saccv[grp][16 + l] * w;
            a2 += saccv[grp][32 + l] * w;
        }
        float v0 = a0 + node_v[(size_t)n * 384 + tt];
        float v1 = a1 + node_v[(size_t)n * 384 + 128 + tt];
        float v2 = a2 + node_v[(size_t)n * 384 + 256 + tt];
        float vn = sqrtf(v0 * v0 + v1 * v1 + v2 * v2);
        float sc = s_cns[tt] / (vn + 1e-8f);
        size_t base = 6400000ull + (size_t)n * 384;
        out[base + tt]       = v0 * sc;
        out[base + 128 + tt] = v1 * sc;
        out[base + 256 + tt] = v2 * sc;
        __syncthreads();
    }
}

// ============================================================================
extern "C" void kernel_launch(void* const* d_in, const int* in_sizes, int n_in,
                              void* d_out, int out_size)
{
    const float* node_s  = (const float*)d_in[0];
    const float* node_v  = (const float*)d_in[1];
    const float* edge_s  = (const float*)d_in[2];
    const float* edge_v  = (const float*)d_in[3];
    const float* dist    = (const float*)d_in[4];
    const float* vctr    = (const float*)d_in[5];
    const int*   src     = (const int*)d_in[6];
    const int*   dst     = (const int*)d_in[7];
    const float* ns_in_w = (const float*)d_in[8];
    const float* ns_in_b = (const float*)d_in[9];
    const float* nv_in_w = (const float*)d_in[10];
    const float* en_w    = (const float*)d_in[11];
    const float* en_b    = (const float*)d_in[12];
    const float* tp_w    = (const float*)d_in[13];
    const float* tp_b    = (const float*)d_in[14];
    const float* gate_w1 = (const float*)d_in[15];
    const float* gate_b1 = (const float*)d_in[16];
    const float* gate_w2 = (const float*)d_in[17];
    const float* gate_b2 = (const float*)d_in[18];
    const float* tv_w    = (const float*)d_in[19];
    const float* tv_b    = (const float*)d_in[20];
    const float* out_nv_w= (const float*)d_in[21];
    const float* ons_w1  = (const float*)d_in[22];
    const float* ons_b1  = (const float*)d_in[23];
    const float* ons_w2  = (const float*)d_in[24];
    const float* ons_b2  = (const float*)d_in[25];
    const float* ln_gamma= (const float*)d_in[26];
    const float* ln_beta = (const float*)d_in[27];
    const float* cn_scale= (const float*)d_in[28];

    float* out = (float*)d_out;
    float* out_es = out + 25600000ull;
    float* out_ev = out + 51200000ull;

    k_node_in<<<K1_BLOCKS, 256>>>(node_s, node_v, ns_in_w, ns_in_b, nv_in_w, en_w, en_b);
    k_edge<<<N_EDGES / 64, 256>>>(edge_s, edge_v, dist, vctr, src, dst,
                                  tp_w, tp_b, gate_w1, gate_b1, gate_w2, gate_b2,
                                  tv_w, tv_b, out_es, out_ev);
    k_node_out<<<N_NODES / K3_NPB, 256>>>(node_s, node_v, out_nv_w, ons_w1, ons_b1,
                                          ons_w2, ons_b2, ln_gamma, ln_beta, cn_scale, out);
}

// round 6
// speedup vs baseline: 1.2592x; 1.0042x over previous
#include <cuda_runtime.h>
#include <math.h>
#include <stdint.h>

#define N_NODES 50000
#define N_EDGES 1600000
#define G 128
#define LG 16
#define PI_F 3.14159265358979323846f

typedef unsigned long long u64;

// ---- scratch (device globals; no allocation allowed) ----
__device__ __align__(16) float g_a[N_NODES * LG];
__device__ __align__(16) float g_b[N_NODES * LG];
__device__ __align__(16) float g_nv[N_NODES * 3 * LG];
__device__ __align__(16) float g_acc_s[N_NODES * LG];
__device__ __align__(16) float g_acc_v[N_NODES * 3 * LG];

__device__ __forceinline__ float siluf(float x) { return x / (1.f + __expf(-x)); }

__device__ __forceinline__ void red4(float* p, float a, float b, float c, float d) {
    asm volatile("red.global.add.v4.f32 [%0], {%1,%2,%3,%4};"
                 :: "l"(p), "f"(a), "f"(b), "f"(c), "f"(d) : "memory");
}

// ---- packed f32x2 helpers ----
__device__ __forceinline__ u64 ffma2(u64 a, u64 b, u64 c) {
    u64 d; asm("fma.rn.f32x2 %0,%1,%2,%3;" : "=l"(d) : "l"(a), "l"(b), "l"(c)); return d;
}
__device__ __forceinline__ u64 mul2(u64 a, u64 b) {
    u64 d; asm("mul.rn.f32x2 %0,%1,%2;" : "=l"(d) : "l"(a), "l"(b)); return d;
}
__device__ __forceinline__ u64 add2(u64 a, u64 b) {
    u64 d; asm("add.rn.f32x2 %0,%1,%2;" : "=l"(d) : "l"(a), "l"(b)); return d;
}
__device__ __forceinline__ u64 pk2(float x, float y) {
    u64 r; asm("mov.b64 %0,{%1,%2};" : "=l"(r) : "f"(x), "f"(y)); return r;
}
__device__ __forceinline__ float2 upk(u64 a) {
    float lo, hi; asm("mov.b64 {%0,%1},%2;" : "=f"(lo), "=f"(hi) : "l"(a));
    return make_float2(lo, hi);
}

// ============================================================================
// Kernel 1: node input projections. 256 thr = 8 j-lanes x 32 node slots;
// each thread computes outputs j and j+8 sharing the row loads (halves LDG).
// ============================================================================
#define WPAD 130
#define K1_TILES ((N_NODES + 31) / 32)   // 1563 (last partial)
#define K1_BLOCKS 592

__global__ void __launch_bounds__(256) k_node_in(
    const float* __restrict__ node_s, const float* __restrict__ node_v,
    const float* __restrict__ ns_w, const float* __restrict__ ns_b,
    const float* __restrict__ nv_w, const float* __restrict__ en_w,
    const float* __restrict__ en_b)
{
    __shared__ __align__(16) float s_wsT[16 * WPAD];
    __shared__ __align__(16) float s_wvT[16 * WPAD];
    __shared__ __align__(16) float s_en[512];
    __shared__ float s_sns[32 * 16];
    __shared__ float s_nsb[16], s_enb[16];

    int t = threadIdx.x;

    {
        float4* as4 = (float4*)g_acc_s;
        float4* av4 = (float4*)g_acc_v;
        int idx = blockIdx.x * 256 + t;
        int stride = K1_BLOCKS * 256;
        for (int i = idx; i < 200000; i += stride) as4[i] = make_float4(0.f, 0.f, 0.f, 0.f);
        for (int i = idx; i < 600000; i += stride) av4[i] = make_float4(0.f, 0.f, 0.f, 0.f);
    }

    for (int i = t; i < 2048; i += 256) {
        int gg = i >> 4, j = i & 15;
        s_wsT[j * WPAD + gg] = ns_w[i];
        s_wvT[j * WPAD + gg] = nv_w[i];
    }
    for (int i = t; i < 512; i += 256) s_en[i] = en_w[i];
    if (t < 16) { s_nsb[t] = ns_b[t]; s_enb[t] = en_b[t]; }
    __syncthreads();

    int j = t & 7, slot = t >> 3;          // j and j+8 computed per thread
    const float2* wsA = (const float2*)(s_wsT + j * WPAD);
    const float2* wsB = (const float2*)(s_wsT + (j + 8) * WPAD);
    const float2* wvA = (const float2*)(s_wvT + j * WPAD);
    const float2* wvB = (const float2*)(s_wvT + (j + 8) * WPAD);

    for (int tile = blockIdx.x; tile < K1_TILES; tile += K1_BLOCKS) {
        int n = tile * 32 + slot;
        bool ok = (n < N_NODES);

        if (ok) {
            // scalar dot for outputs j and j+8 (shared row loads)
            {
                const float4* r4 = (const float4*)(node_s + (size_t)n * 128);
                float aA0 = 0.f, aA1 = 0.f, aB0 = 0.f, aB1 = 0.f;
                #pragma unroll 8
                for (int qq = 0; qq < 32; qq++) {
                    float4 r = __ldg(r4 + qq);
                    float2 wa = wsA[2 * qq], wb = wsA[2 * qq + 1];
                    float2 wc = wsB[2 * qq], wd = wsB[2 * qq + 1];
                    aA0 += r.x * wa.x + r.y * wa.y; aA1 += r.z * wb.x + r.w * wb.y;
                    aB0 += r.x * wc.x + r.y * wc.y; aB1 += r.z * wd.x + r.w * wd.y;
                }
                s_sns[slot * 16 + j]     = siluf(aA0 + aA1 + s_nsb[j]);
                s_sns[slot * 16 + j + 8] = siluf(aB0 + aB1 + s_nsb[j + 8]);
            }

            // vector dots (3 components x 2 outputs, shared row loads)
            {
                const float4* v0 = (const float4*)(node_v + (size_t)n * 384);
                const float4* v1 = v0 + 32;
                const float4* v2 = v0 + 64;
                float a0A = 0.f, a1A = 0.f, a2A = 0.f;
                float a0B = 0.f, a1B = 0.f, a2B = 0.f;
                #pragma unroll 8
                for (int qq = 0; qq < 32; qq++) {
                    float2 wa = wvA[2 * qq], wb = wvA[2 * qq + 1];
                    float2 wc = wvB[2 * qq], wd = wvB[2 * qq + 1];
                    float4 r0 = __ldg(v0 + qq), r1 = __ldg(v1 + qq), r2 = __ldg(v2 + qq);
                    a0A += r0.x * wa.x + r0.y * wa.y + r0.z * wb.x + r0.w * wb.y;
                    a1A += r1.x * wa.x + r1.y * wa.y + r1.z * wb.x + r1.w * wb.y;
                    a2A += r2.x * wa.x + r2.y * wa.y + r2.z * wb.x + r2.w * wb.y;
                    a0B += r0.x * wc.x + r0.y * wc.y + r0.z * wd.x + r0.w * wd.y;
                    a1B += r1.x * wc.x + r1.y * wc.y + r1.z * wd.x + r1.w * wd.y;
                    a2B += r2.x * wc.x + r2.y * wc.y + r2.z * wd.x + r2.w * wd.y;
                }
                g_nv[(size_t)n * 48 + j]          = a0A;
                g_nv[(size_t)n * 48 + 16 + j]     = a1A;
                g_nv[(size_t)n * 48 + 32 + j]     = a2A;
                g_nv[(size_t)n * 48 + j + 8]      = a0B;
                g_nv[(size_t)n * 48 + 16 + j + 8] = a1B;
                g_nv[(size_t)n * 48 + 32 + j + 8] = a2B;
            }
        }
        __syncthreads();

        if (ok) {
            float aA = 0.f, bA = s_enb[j];
            float aB = 0.f, bB = s_enb[j + 8];
            #pragma unroll
            for (int k = 0; k < 16; k++) {
                float x = s_sns[slot * 16 + k];
                aA += x * s_en[k * 16 + j];
                bA += x * s_en[(16 + k) * 16 + j];
                aB += x * s_en[k * 16 + j + 8];
                bB += x * s_en[(16 + k) * 16 + j + 8];
            }
            g_a[(size_t)n * 16 + j]     = aA;
            g_b[(size_t)n * 16 + j]     = bA;
            g_a[(size_t)n * 16 + j + 8] = aB;
            g_b[(size_t)n * 16 + j + 8] = bB;
        }
        __syncthreads();
    }
}

// ============================================================================
// Kernel 2: QUAD layout + FULL PREFETCH — every global load issued up front
// (MLP ~11), then the dependent matvec chain, then stores/reductions.
// ============================================================================
#define MATVEC16x4(Y0, Y1, X0, X1, SW, Q)                                    \
    {                                                                        \
        _Pragma("unroll")                                                    \
        for (int k = 0; k < 16; k++) {                                       \
            float2 xp = upk(((k & 2) ? (X1) : (X0)));                        \
            float xs = (k & 1) ? xp.y : xp.x;                                \
            float xk = __shfl_sync(0xffffffffu, xs, k >> 2, 4);              \
            u64 xx = pk2(xk, xk);                                            \
            ulonglong2 w = ((const ulonglong2*)((SW) + k * 16))[Q];          \
            (Y0) = ffma2(xx, w.x, (Y0));                                     \
            (Y1) = ffma2(xx, w.y, (Y1));                                     \
        }                                                                    \
    }

__global__ void __launch_bounds__(256) k_edge(
    const float* __restrict__ edge_s, const float* __restrict__ edge_v,
    const float* __restrict__ dist,   const float* __restrict__ vctr,
    const int* __restrict__ src,      const int* __restrict__ dst,
    const float* __restrict__ tp_w, const float* __restrict__ tp_b,
    const float* __restrict__ g1w,  const float* __restrict__ g1b,
    const float* __restrict__ g2w,  const float* __restrict__ g2b,
    const float* __restrict__ tvw,  const float* __restrict__ tvb,
    float* __restrict__ out_es, float* __restrict__ out_ev)
{
    __shared__ __align__(16) float s_tp[256], s_g1[256], s_g2[256], s_tv[768];
    __shared__ __align__(16) float s_tpb[16], s_g1b[16], s_g2b[16], s_tvb[48];
    int t = threadIdx.x;
    if (t < 256) { s_tp[t] = tp_w[t]; s_g1[t] = g1w[t]; s_g2[t] = g2w[t]; }
    for (int i = t; i < 768; i += 256) s_tv[i] = tvw[i];
    if (t < 16) { s_tpb[t] = tp_b[t]; s_g1b[t] = g1b[t]; s_g2b[t] = g2b[t]; }
    if (t < 48) s_tvb[t] = tvb[t];
    __syncthreads();

    int q = t & 3;
    int e = blockIdx.x * 64 + (t >> 2);

    // ---------- PREFETCH: issue every global load now ----------
    int s = src[e], d = dst[e];
    float dd = dist[e];
    float vc0 = vctr[(size_t)e * 3];
    float vc1 = vctr[(size_t)e * 3 + 1];
    float vc2 = vctr[(size_t)e * 3 + 2];

    ulonglong2 eslv = ((const ulonglong2*)edge_s)[(size_t)e * 4 + q];
    ulonglong2 ev0  = ((const ulonglong2*)(edge_v + (size_t)e * 48))[q];
    ulonglong2 ev1  = ((const ulonglong2*)(edge_v + (size_t)e * 48 + 16))[q];
    ulonglong2 ev2  = ((const ulonglong2*)(edge_v + (size_t)e * 48 + 32))[q];

    ulonglong2 va = __ldg((const ulonglong2*)g_a + (size_t)s * 4 + q);
    ulonglong2 vb = __ldg((const ulonglong2*)g_b + (size_t)d * 4 + q);
    ulonglong2 nv0 = __ldg((const ulonglong2*)(g_nv + (size_t)s * 48) + q);
    ulonglong2 nv1 = __ldg((const ulonglong2*)(g_nv + (size_t)s * 48 + 16) + q);
    ulonglong2 nv2 = __ldg((const ulonglong2*)(g_nv + (size_t)s * 48 + 32) + q);
    // ------------------------------------------------------------

    u64 esl0 = eslv.x, esl1 = eslv.y;
    u64 en0 = add2(va.x, vb.x), en1 = add2(va.y, vb.y);

    // tm = en * (edge_s @ tp_w + tp_b)
    u64 tm0, tm1;
    { ulonglong2 b = ((const ulonglong2*)s_tpb)[q]; tm0 = b.x; tm1 = b.y; }
    MATVEC16x4(tm0, tm1, esl0, esl1, s_tp, q);
    tm0 = mul2(tm0, en0); tm1 = mul2(tm1, en1);

    // h = silu(tm @ g1 + b1)
    u64 h0, h1;
    { ulonglong2 b = ((const ulonglong2*)s_g1b)[q]; h0 = b.x; h1 = b.y; }
    MATVEC16x4(h0, h1, tm0, tm1, s_g1, q);
    {
        float2 a = upk(h0), b = upk(h1);
        h0 = pk2(siluf(a.x), siluf(a.y));
        h1 = pk2(siluf(b.x), siluf(b.y));
    }

    // gt = h @ g2 + b2
    u64 gt0, gt1;
    { ulonglong2 b = ((const ulonglong2*)s_g2b)[q]; gt0 = b.x; gt1 = b.y; }
    MATVEC16x4(gt0, gt1, h0, h1, s_g2, q);

    float C = 0.5f * (__cosf(PI_F * dd * 0.1f) + 1.f) * (dd < 10.f ? 1.f : 0.f);

    u64 es0, es1;
    {
        float2 tv0 = upk(tm0), tv1 = upk(tm1);
        float2 gv0 = upk(gt0), gv1 = upk(gt1);
        es0 = pk2(tv0.x * (1.f / (1.f + __expf(-gv0.x))) * C,
                  tv0.y * (1.f / (1.f + __expf(-gv0.y))) * C);
        es1 = pk2(tv1.x * (1.f / (1.f + __expf(-gv1.x))) * C,
                  tv1.y * (1.f / (1.f + __expf(-gv1.y))) * C);
    }

    // edge_s_out + scatter
    {
        ulonglong2 o;
        o.x = add2(es0, esl0);
        o.y = add2(es1, esl1);
        ((ulonglong2*)out_es)[(size_t)e * 4 + q] = o;
        float2 a = upk(es0), b = upk(es1);
        red4(g_acc_s + (size_t)d * 16 + q * 4, a.x, a.y, b.x, b.y);
    }

    // ter = (es @ tv_w + tv_b) * C
    u64 tt0, tt1, te0, te1, tr0, tr1;
    {
        ulonglong2 bt = ((const ulonglong2*)(s_tvb))[q];
        ulonglong2 be = ((const ulonglong2*)(s_tvb + 16))[q];
        ulonglong2 br = ((const ulonglong2*)(s_tvb + 32))[q];
        tt0 = bt.x; tt1 = bt.y; te0 = be.x; te1 = be.y; tr0 = br.x; tr1 = br.y;
    }
    #pragma unroll
    for (int k = 0; k < 16; k++) {
        float2 xp = upk((k & 2) ? es1 : es0);
        float xs = (k & 1) ? xp.y : xp.x;
        float xk = __shfl_sync(0xffffffffu, xs, k >> 2, 4);
        u64 xx = pk2(xk, xk);
        ulonglong2 wt = ((const ulonglong2*)(s_tv + k * 48))[q];
        ulonglong2 we = ((const ulonglong2*)(s_tv + k * 48 + 16))[q];
        ulonglong2 wr = ((const ulonglong2*)(s_tv + k * 48 + 32))[q];
        tt0 = ffma2(xx, wt.x, tt0); tt1 = ffma2(xx, wt.y, tt1);
        te0 = ffma2(xx, we.x, te0); te1 = ffma2(xx, we.y, te1);
        tr0 = ffma2(xx, wr.x, tr0); tr1 = ffma2(xx, wr.y, tr1);
    }
    {
        u64 CC = pk2(C, C);
        tt0 = mul2(tt0, CC); tt1 = mul2(tt1, CC);
        te0 = mul2(te0, CC); te1 = mul2(te1, CC);
        tr0 = mul2(tr0, CC); tr1 = mul2(tr1, CC);
    }

    // vector update using prefetched ev/nv
    {
        u64 vx = pk2(vc0, vc0);
        u64 u0 = ffma2(ev0.x, tt0, ffma2(nv0.x, te0, mul2(vx, tr0)));
        u64 u1 = ffma2(ev0.y, tt1, ffma2(nv0.y, te1, mul2(vx, tr1)));
        ulonglong2 o; o.x = add2(u0, ev0.x); o.y = add2(u1, ev0.y);
        ((ulonglong2*)(out_ev + (size_t)e * 48))[q] = o;
        float2 a = upk(u0), b = upk(u1);
        red4(g_acc_v + (size_t)d * 48 + q * 4, a.x, a.y, b.x, b.y);
    }
    {
        u64 vx = pk2(vc1, vc1);
        u64 u0 = ffma2(ev1.x, tt0, ffma2(nv1.x, te0, mul2(vx, tr0)));
        u64 u1 = ffma2(ev1.y, tt1, ffma2(nv1.y, te1, mul2(vx, tr1)));
        ulonglong2 o; o.x = add2(u0, ev1.x); o.y = add2(u1, ev1.y);
        ((ulonglong2*)(out_ev + (size_t)e * 48 + 16))[q] = o;
        float2 a = upk(u0), b = upk(u1);
        red4(g_acc_v + (size_t)d * 48 + 16 + q * 4, a.x, a.y, b.x, b.y);
    }
    {
        u64 vx = pk2(vc2, vc2);
        u64 u0 = ffma2(ev2.x, tt0, ffma2(nv2.x, te0, mul2(vx, tr0)));
        u64 u1 = ffma2(ev2.y, tt1, ffma2(nv2.y, te1, mul2(vx, tr1)));
        ulonglong2 o; o.x = add2(u0, ev2.x); o.y = add2(u1, ev2.y);
        ((ulonglong2*)(out_ev + (size_t)e * 48 + 32))[q] = o;
        float2 a = upk(u0), b = upk(u1);
        red4(g_acc_v + (size_t)d * 48 + 32 + q * 4, a.x, a.y, b.x, b.y);
    }
}

// ============================================================================
// Kernel 3: node epilogue (unchanged)
// ============================================================================
#define K3_NPB 16
__global__ void __launch_bounds__(256) k_node_out(
    const float* __restrict__ node_s, const float* __restrict__ node_v,
    const float* __restrict__ onw,
    const float* __restrict__ w1, const float* __restrict__ b1,
    const float* __restrict__ w2, const float* __restrict__ b2,
    const float* __restrict__ gamma, const float* __restrict__ beta,
    const float* __restrict__ cns, float* __restrict__ out)
{
    __shared__ __align__(16) float s_w1[512], s_w2[2048], s_onw[2048];
    __shared__ float s_b1[16], s_b2[128], s_gam[128], s_bet[128], s_cns[128];
    __shared__ float sacc[2][16], snvn[2][16], sh[2][16], saccv[2][48];
    __shared__ float rs1[2][4], rs2[2][4];

    int t = threadIdx.x;
    for (int i = t; i < 512; i += 256) s_w1[i] = w1[i];
    for (int i = t; i < 2048; i += 256) { s_w2[i] = w2[i]; s_onw[i] = onw[i]; }
    if (t < 16) s_b1[t] = b1[t];
    if (t < 128) { s_b2[t] = b2[t]; s_gam[t] = gamma[t]; s_bet[t] = beta[t]; s_cns[t] = cns[t]; }
    __syncthreads();

    int grp = t >> 7, tt = t & 127;
    int n0 = blockIdx.x * K3_NPB;

    for (int it = 0; it < K3_NPB; it += 2) {
        int n = n0 + it + grp;

        if (tt < 16) sacc[grp][tt] = g_acc_s[(size_t)n * 16 + tt];
        else if (tt < 64) saccv[grp][tt - 16] = g_acc_v[(size_t)n * 48 + (tt - 16)];
        else if (tt < 80) {
            int l = tt - 64;
            float a = g_nv[(size_t)n * 48 + l];
            float b = g_nv[(size_t)n * 48 + 16 + l];
            float c = g_nv[(size_t)n * 48 + 32 + l];
            snvn[grp][l] = sqrtf(a * a + b * b + c * c);
        }
        __syncthreads();

        if (tt < 16) {
            float acc = s_b1[tt];
            #pragma unroll
            for (int k = 0; k < 16; k++) acc += sacc[grp][k] * s_w1[k * 16 + tt];
            #pragma unroll
            for (int k = 0; k < 16; k++) acc += snvn[grp][k] * s_w1[(16 + k) * 16 + tt];
            sh[grp][tt] = siluf(acc);
        }
        __syncthreads();

        float nsu = s_b2[tt];
        #pragma unroll
        for (int l = 0; l < 16; l++) nsu += sh[grp][l] * s_w2[l * 128 + tt];
        float xv = nsu + node_s[(size_t)n * 128 + tt];

        float s1 = xv, s2 = xv * xv;
        #pragma unroll
        for (int o = 16; o > 0; o >>= 1) {
            s1 += __shfl_down_sync(0xffffffffu, s1, o);
            s2 += __shfl_down_sync(0xffffffffu, s2, o);
        }
        if ((tt & 31) == 0) { rs1[grp][tt >> 5] = s1; rs2[grp][tt >> 5] = s2; }
        __syncthreads();
        float ts1 = rs1[grp][0] + rs1[grp][1] + rs1[grp][2] + rs1[grp][3];
        float ts2 = rs2[grp][0] + rs2[grp][1] + rs2[grp][2] + rs2[grp][3];
        float mu = ts1 * (1.f / 128.f);
        float var = ts2 * (1.f / 128.f) - mu * mu;
        out[(size_t)n * 128 + tt] = (xv - mu) * rsqrtf(var + 1e-5f) * s_gam[tt] + s_bet[tt];

        float a0 = 0.f, a1 = 0.f, a2 = 0.f;
        #pragma unroll
        for (int l = 0; l < 16; l++) {
            float w = s_onw[l * 128 + tt];
            a0 += saccv[grp][l] * w;
            a1 += saccv[grp][16 + l] * w;
            a2 += saccv[grp][32 + l] * w;
        }
        float v0 = a0 + node_v[(size_t)n * 384 + tt];
        float v1 = a1 + node_v[(size_t)n * 384 + 128 + tt];
        float v2 = a2 + node_v[(size_t)n * 384 + 256 + tt];
        float vn = sqrtf(v0 * v0 + v1 * v1 + v2 * v2);
        float sc = s_cns[tt] / (vn + 1e-8f);
        size_t base = 6400000ull + (size_t)n * 384;
        out[base + tt]       = v0 * sc;
        out[base + 128 + tt] = v1 * sc;
        out[base + 256 + tt] = v2 * sc;
        __syncthreads();
    }
}

// ============================================================================
extern "C" void kernel_launch(void* const* d_in, const int* in_sizes, int n_in,
                              void* d_out, int out_size)
{
    const float* node_s  = (const float*)d_in[0];
    const float* node_v  = (const float*)d_in[1];
    const float* edge_s  = (const float*)d_in[2];
    const float* edge_v  = (const float*)d_in[3];
    const float* dist    = (const float*)d_in[4];
    const float* vctr    = (const float*)d_in[5];
    const int*   src     = (const int*)d_in[6];
    const int*   dst     = (const int*)d_in[7];
    const float* ns_in_w = (const float*)d_in[8];
    const float* ns_in_b = (const float*)d_in[9];
    const float* nv_in_w = (const float*)d_in[10];
    const float* en_w    = (const float*)d_in[11];
    const float* en_b    = (const float*)d_in[12];
    const float* tp_w    = (const float*)d_in[13];
    const float* tp_b    = (const float*)d_in[14];
    const float* gate_w1 = (const float*)d_in[15];
    const float* gate_b1 = (const float*)d_in[16];
    const float* gate_w2 = (const float*)d_in[17];
    const float* gate_b2 = (const float*)d_in[18];
    const float* tv_w    = (const float*)d_in[19];
    const float* tv_b    = (const float*)d_in[20];
    const float* out_nv_w= (const float*)d_in[21];
    const float* ons_w1  = (const float*)d_in[22];
    const float* ons_b1  = (const float*)d_in[23];
    const float* ons_w2  = (const float*)d_in[24];
    const float* ons_b2  = (const float*)d_in[25];
    const float* ln_gamma= (const float*)d_in[26];
    const float* ln_beta = (const float*)d_in[27];
    const float* cn_scale= (const float*)d_in[28];

    float* out = (float*)d_out;
    float* out_es = out + 25600000ull;
    float* out_ev = out + 51200000ull;

    k_node_in<<<K1_BLOCKS, 256>>>(node_s, node_v, ns_in_w, ns_in_b, nv_in_w, en_w, en_b);
    k_edge<<<N_EDGES / 64, 256>>>(edge_s, edge_v, dist, vctr, src, dst,
                                  tp_w, tp_b, gate_w1, gate_b1, gate_w2, gate_b2,
                                  tv_w, tv_b, out_es, out_ev);
    k_node_out<<<N_NODES / K3_NPB, 256>>>(node_s, node_v, out_nv_w, ons_w1, ons_b1,
                                          ons_w2, ons_b2, ln_gamma, ln_beta, cn_scale, out);
}

// round 7
// speedup vs baseline: 1.4848x; 1.1791x over previous
#include <cuda_runtime.h>
#include <math.h>
#include <stdint.h>

#define N_NODES 50000
#define N_EDGES 1600000
#define G 128
#define LG 16
#define PI_F 3.14159265358979323846f

typedef unsigned long long u64;

// ---- scratch (device globals; no allocation allowed) ----
__device__ __align__(16) float g_a[N_NODES * LG];
__device__ __align__(16) float g_b[N_NODES * LG];
__device__ __align__(16) float g_nv[N_NODES * 3 * LG];
__device__ __align__(16) float g_acc_s[N_NODES * LG];
__device__ __align__(16) float g_acc_v[N_NODES * 3 * LG];

__device__ __forceinline__ float siluf(float x) { return x / (1.f + __expf(-x)); }

__device__ __forceinline__ void red4(float* p, float a, float b, float c, float d) {
    asm volatile("red.global.add.v4.f32 [%0], {%1,%2,%3,%4};"
                 :: "l"(p), "f"(a), "f"(b), "f"(c), "f"(d) : "memory");
}

// ---- packed f32x2 helpers ----
__device__ __forceinline__ u64 ffma2(u64 a, u64 b, u64 c) {
    u64 d; asm("fma.rn.f32x2 %0,%1,%2,%3;" : "=l"(d) : "l"(a), "l"(b), "l"(c)); return d;
}
__device__ __forceinline__ u64 mul2(u64 a, u64 b) {
    u64 d; asm("mul.rn.f32x2 %0,%1,%2;" : "=l"(d) : "l"(a), "l"(b)); return d;
}
__device__ __forceinline__ u64 add2(u64 a, u64 b) {
    u64 d; asm("add.rn.f32x2 %0,%1,%2;" : "=l"(d) : "l"(a), "l"(b)); return d;
}
__device__ __forceinline__ u64 pk2(float x, float y) {
    u64 r; asm("mov.b64 %0,{%1,%2};" : "=l"(r) : "f"(x), "f"(y)); return r;
}
__device__ __forceinline__ float2 upk(u64 a) {
    float lo, hi; asm("mov.b64 {%0,%1},%2;" : "=f"(lo), "=f"(hi) : "l"(a));
    return make_float2(lo, hi);
}

// ============================================================================
// Kernel 1: node input projections (unchanged from R6 — 67us)
// ============================================================================
#define WPAD 130
#define K1_TILES ((N_NODES + 31) / 32)
#define K1_BLOCKS 592

__global__ void __launch_bounds__(256) k_node_in(
    const float* __restrict__ node_s, const float* __restrict__ node_v,
    const float* __restrict__ ns_w, const float* __restrict__ ns_b,
    const float* __restrict__ nv_w, const float* __restrict__ en_w,
    const float* __restrict__ en_b)
{
    __shared__ __align__(16) float s_wsT[16 * WPAD];
    __shared__ __align__(16) float s_wvT[16 * WPAD];
    __shared__ __align__(16) float s_en[512];
    __shared__ float s_sns[32 * 16];
    __shared__ float s_nsb[16], s_enb[16];

    int t = threadIdx.x;

    {
        float4* as4 = (float4*)g_acc_s;
        float4* av4 = (float4*)g_acc_v;
        int idx = blockIdx.x * 256 + t;
        int stride = K1_BLOCKS * 256;
        for (int i = idx; i < 200000; i += stride) as4[i] = make_float4(0.f, 0.f, 0.f, 0.f);
        for (int i = idx; i < 600000; i += stride) av4[i] = make_float4(0.f, 0.f, 0.f, 0.f);
    }

    for (int i = t; i < 2048; i += 256) {
        int gg = i >> 4, j = i & 15;
        s_wsT[j * WPAD + gg] = ns_w[i];
        s_wvT[j * WPAD + gg] = nv_w[i];
    }
    for (int i = t; i < 512; i += 256) s_en[i] = en_w[i];
    if (t < 16) { s_nsb[t] = ns_b[t]; s_enb[t] = en_b[t]; }
    __syncthreads();

    int j = t & 7, slot = t >> 3;
    const float2* wsA = (const float2*)(s_wsT + j * WPAD);
    const float2* wsB = (const float2*)(s_wsT + (j + 8) * WPAD);
    const float2* wvA = (const float2*)(s_wvT + j * WPAD);
    const float2* wvB = (const float2*)(s_wvT + (j + 8) * WPAD);

    for (int tile = blockIdx.x; tile < K1_TILES; tile += K1_BLOCKS) {
        int n = tile * 32 + slot;
        bool ok = (n < N_NODES);

        if (ok) {
            {
                const float4* r4 = (const float4*)(node_s + (size_t)n * 128);
                float aA0 = 0.f, aA1 = 0.f, aB0 = 0.f, aB1 = 0.f;
                #pragma unroll 8
                for (int qq = 0; qq < 32; qq++) {
                    float4 r = __ldg(r4 + qq);
                    float2 wa = wsA[2 * qq], wb = wsA[2 * qq + 1];
                    float2 wc = wsB[2 * qq], wd = wsB[2 * qq + 1];
                    aA0 += r.x * wa.x + r.y * wa.y; aA1 += r.z * wb.x + r.w * wb.y;
                    aB0 += r.x * wc.x + r.y * wc.y; aB1 += r.z * wd.x + r.w * wd.y;
                }
                s_sns[slot * 16 + j]     = siluf(aA0 + aA1 + s_nsb[j]);
                s_sns[slot * 16 + j + 8] = siluf(aB0 + aB1 + s_nsb[j + 8]);
            }
            {
                const float4* v0 = (const float4*)(node_v + (size_t)n * 384);
                const float4* v1 = v0 + 32;
                const float4* v2 = v0 + 64;
                float a0A = 0.f, a1A = 0.f, a2A = 0.f;
                float a0B = 0.f, a1B = 0.f, a2B = 0.f;
                #pragma unroll 8
                for (int qq = 0; qq < 32; qq++) {
                    float2 wa = wvA[2 * qq], wb = wvA[2 * qq + 1];
                    float2 wc = wvB[2 * qq], wd = wvB[2 * qq + 1];
                    float4 r0 = __ldg(v0 + qq), r1 = __ldg(v1 + qq), r2 = __ldg(v2 + qq);
                    a0A += r0.x * wa.x + r0.y * wa.y + r0.z * wb.x + r0.w * wb.y;
                    a1A += r1.x * wa.x + r1.y * wa.y + r1.z * wb.x + r1.w * wb.y;
                    a2A += r2.x * wa.x + r2.y * wa.y + r2.z * wb.x + r2.w * wb.y;
                    a0B += r0.x * wc.x + r0.y * wc.y + r0.z * wd.x + r0.w * wd.y;
                    a1B += r1.x * wc.x + r1.y * wc.y + r1.z * wd.x + r1.w * wd.y;
                    a2B += r2.x * wc.x + r2.y * wc.y + r2.z * wd.x + r2.w * wd.y;
                }
                g_nv[(size_t)n * 48 + j]          = a0A;
                g_nv[(size_t)n * 48 + 16 + j]     = a1A;
                g_nv[(size_t)n * 48 + 32 + j]     = a2A;
                g_nv[(size_t)n * 48 + j + 8]      = a0B;
                g_nv[(size_t)n * 48 + 16 + j + 8] = a1B;
                g_nv[(size_t)n * 48 + 32 + j + 8] = a2B;
            }
        }
        __syncthreads();

        if (ok) {
            float aA = 0.f, bA = s_enb[j];
            float aB = 0.f, bB = s_enb[j + 8];
            #pragma unroll
            for (int k = 0; k < 16; k++) {
                float x = s_sns[slot * 16 + k];
                aA += x * s_en[k * 16 + j];
                bA += x * s_en[(16 + k) * 16 + j];
                aB += x * s_en[k * 16 + j + 8];
                bB += x * s_en[(16 + k) * 16 + j + 8];
            }
            g_a[(size_t)n * 16 + j]     = aA;
            g_b[(size_t)n * 16 + j]     = bA;
            g_a[(size_t)n * 16 + j + 8] = aB;
            g_b[(size_t)n * 16 + j + 8] = bB;
        }
        __syncthreads();
    }
}

// ============================================================================
// Kernel 2: QUAD layout, 2 EDGES PER THREAD — each weight LDS.128 feeds both
// edges (8 FFMA2 per LDS instead of 4). Block of 256 covers 128 edges:
// thread (slot,q) handles edges e0=blk*128+slot and e1=e0+64.
// ============================================================================

// paired matvec: y(edge0), z(edge1) += x(edge) @ W, weights loaded once
#define MATVEC16x4P(Y0, Y1, Z0, Z1, X0, X1, W0, W1, SW, Q)                   \
    {                                                                        \
        _Pragma("unroll")                                                    \
        for (int k = 0; k < 16; k++) {                                       \
            float2 xpa = upk(((k & 2) ? (X1) : (X0)));                       \
            float2 xpb = upk(((k & 2) ? (W1) : (W0)));                       \
            float xsa = (k & 1) ? xpa.y : xpa.x;                             \
            float xsb = (k & 1) ? xpb.y : xpb.x;                             \
            float xka = __shfl_sync(0xffffffffu, xsa, k >> 2, 4);            \
            float xkb = __shfl_sync(0xffffffffu, xsb, k >> 2, 4);            \
            u64 xxa = pk2(xka, xka);                                         \
            u64 xxb = pk2(xkb, xkb);                                         \
            ulonglong2 w = ((const ulonglong2*)((SW) + k * 16))[Q];          \
            (Y0) = ffma2(xxa, w.x, (Y0));                                    \
            (Y1) = ffma2(xxa, w.y, (Y1));                                    \
            (Z0) = ffma2(xxb, w.x, (Z0));                                    \
            (Z1) = ffma2(xxb, w.y, (Z1));                                    \
        }                                                                    \
    }

__global__ void __launch_bounds__(256) k_edge(
    const float* __restrict__ edge_s, const float* __restrict__ edge_v,
    const float* __restrict__ dist,   const float* __restrict__ vctr,
    const int* __restrict__ src,      const int* __restrict__ dst,
    const float* __restrict__ tp_w, const float* __restrict__ tp_b,
    const float* __restrict__ g1w,  const float* __restrict__ g1b,
    const float* __restrict__ g2w,  const float* __restrict__ g2b,
    const float* __restrict__ tvw,  const float* __restrict__ tvb,
    float* __restrict__ out_es, float* __restrict__ out_ev)
{
    __shared__ __align__(16) float s_tp[256], s_g1[256], s_g2[256], s_tv[768];
    __shared__ __align__(16) float s_tpb[16], s_g1b[16], s_g2b[16], s_tvb[48];
    int t = threadIdx.x;
    { s_tp[t] = tp_w[t]; s_g1[t] = g1w[t]; s_g2[t] = g2w[t]; }
    for (int i = t; i < 768; i += 256) s_tv[i] = tvw[i];
    if (t < 16) { s_tpb[t] = tp_b[t]; s_g1b[t] = g1b[t]; s_g2b[t] = g2b[t]; }
    if (t < 48) s_tvb[t] = tvb[t];
    __syncthreads();

    int q = t & 3;
    int slot = t >> 2;                      // 0..63
    int e0 = blockIdx.x * 128 + slot;
    int e1 = e0 + 64;

    int s0 = src[e0], d0 = dst[e0];
    int s1 = src[e1], d1 = dst[e1];
    float dd0 = dist[e0], dd1 = dist[e1];

    // edge_s rows (this lane's 4 channels per edge)
    ulonglong2 ea = ((const ulonglong2*)edge_s)[(size_t)e0 * 4 + q];
    ulonglong2 eb = ((const ulonglong2*)edge_s)[(size_t)e1 * 4 + q];
    u64 esl00 = ea.x, esl01 = ea.y;
    u64 esl10 = eb.x, esl11 = eb.y;

    // gathers: a[src]+b[dst] per edge
    u64 en00, en01, en10, en11;
    {
        ulonglong2 va0 = __ldg((const ulonglong2*)g_a + (size_t)s0 * 4 + q);
        ulonglong2 vb0 = __ldg((const ulonglong2*)g_b + (size_t)d0 * 4 + q);
        ulonglong2 va1 = __ldg((const ulonglong2*)g_a + (size_t)s1 * 4 + q);
        ulonglong2 vb1 = __ldg((const ulonglong2*)g_b + (size_t)d1 * 4 + q);
        en00 = add2(va0.x, vb0.x); en01 = add2(va0.y, vb0.y);
        en10 = add2(va1.x, vb1.x); en11 = add2(va1.y, vb1.y);
    }

    // tm = en * (edge_s @ tp_w + tp_b)   (both edges, shared weight LDS)
    u64 tm00, tm01, tm10, tm11;
    { ulonglong2 b = ((const ulonglong2*)s_tpb)[q]; tm00 = b.x; tm01 = b.y; tm10 = b.x; tm11 = b.y; }
    MATVEC16x4P(tm00, tm01, tm10, tm11, esl00, esl01, esl10, esl11, s_tp, q);
    tm00 = mul2(tm00, en00); tm01 = mul2(tm01, en01);
    tm10 = mul2(tm10, en10); tm11 = mul2(tm11, en11);

    // h = silu(tm @ g1 + b1)
    u64 h00, h01, h10, h11;
    { ulonglong2 b = ((const ulonglong2*)s_g1b)[q]; h00 = b.x; h01 = b.y; h10 = b.x; h11 = b.y; }
    MATVEC16x4P(h00, h01, h10, h11, tm00, tm01, tm10, tm11, s_g1, q);
    {
        float2 a0 = upk(h00), a1 = upk(h01), b0 = upk(h10), b1 = upk(h11);
        h00 = pk2(siluf(a0.x), siluf(a0.y));
        h01 = pk2(siluf(a1.x), siluf(a1.y));
        h10 = pk2(siluf(b0.x), siluf(b0.y));
        h11 = pk2(siluf(b1.x), siluf(b1.y));
    }

    // gt = h @ g2 + b2
    u64 gt00, gt01, gt10, gt11;
    { ulonglong2 b = ((const ulonglong2*)s_g2b)[q]; gt00 = b.x; gt01 = b.y; gt10 = b.x; gt11 = b.y; }
    MATVEC16x4P(gt00, gt01, gt10, gt11, h00, h01, h10, h11, s_g2, q);

    float C0 = 0.5f * (__cosf(PI_F * dd0 * 0.1f) + 1.f) * (dd0 < 10.f ? 1.f : 0.f);
    float C1 = 0.5f * (__cosf(PI_F * dd1 * 0.1f) + 1.f) * (dd1 < 10.f ? 1.f : 0.f);

    // es = tm * sigmoid(gt) * C
    u64 es00, es01, es10, es11;
    {
        float2 t0 = upk(tm00), t1 = upk(tm01), g0 = upk(gt00), g1v = upk(gt01);
        es00 = pk2(t0.x * (1.f / (1.f + __expf(-g0.x))) * C0,
                   t0.y * (1.f / (1.f + __expf(-g0.y))) * C0);
        es01 = pk2(t1.x * (1.f / (1.f + __expf(-g1v.x))) * C0,
                   t1.y * (1.f / (1.f + __expf(-g1v.y))) * C0);
        float2 u0 = upk(tm10), u1 = upk(tm11), f0 = upk(gt10), f1 = upk(gt11);
        es10 = pk2(u0.x * (1.f / (1.f + __expf(-f0.x))) * C1,
                   u0.y * (1.f / (1.f + __expf(-f0.y))) * C1);
        es11 = pk2(u1.x * (1.f / (1.f + __expf(-f1.x))) * C1,
                   u1.y * (1.f / (1.f + __expf(-f1.y))) * C1);
    }

    // edge_s_out + scatter (both edges)
    {
        ulonglong2 o0; o0.x = add2(es00, esl00); o0.y = add2(es01, esl01);
        ((ulonglong2*)out_es)[(size_t)e0 * 4 + q] = o0;
        ulonglong2 o1; o1.x = add2(es10, esl10); o1.y = add2(es11, esl11);
        ((ulonglong2*)out_es)[(size_t)e1 * 4 + q] = o1;
        float2 a0 = upk(es00), a1 = upk(es01);
        red4(g_acc_s + (size_t)d0 * 16 + q * 4, a0.x, a0.y, a1.x, a1.y);
        float2 b0 = upk(es10), b1 = upk(es11);
        red4(g_acc_s + (size_t)d1 * 16 + q * 4, b0.x, b0.y, b1.x, b1.y);
    }

    // ter = (es @ tv_w + tv_b) * C (both edges, shared weight LDS)
    u64 at0, at1, ae0, ae1, ar0, ar1;   // edge0
    u64 bt0, bt1, be0, be1, br0, br1;   // edge1
    {
        ulonglong2 w0 = ((const ulonglong2*)(s_tvb))[q];
        ulonglong2 w1 = ((const ulonglong2*)(s_tvb + 16))[q];
        ulonglong2 w2 = ((const ulonglong2*)(s_tvb + 32))[q];
        at0 = w0.x; at1 = w0.y; ae0 = w1.x; ae1 = w1.y; ar0 = w2.x; ar1 = w2.y;
        bt0 = w0.x; bt1 = w0.y; be0 = w1.x; be1 = w1.y; br0 = w2.x; br1 = w2.y;
    }
    #pragma unroll
    for (int k = 0; k < 16; k++) {
        float2 xpa = upk((k & 2) ? es01 : es00);
        float2 xpb = upk((k & 2) ? es11 : es10);
        float xsa = (k & 1) ? xpa.y : xpa.x;
        float xsb = (k & 1) ? xpb.y : xpb.x;
        float xka = __shfl_sync(0xffffffffu, xsa, k >> 2, 4);
        float xkb = __shfl_sync(0xffffffffu, xsb, k >> 2, 4);
        u64 xxa = pk2(xka, xka), xxb = pk2(xkb, xkb);
        ulonglong2 wt = ((const ulonglong2*)(s_tv + k * 48))[q];
        ulonglong2 we = ((const ulonglong2*)(s_tv + k * 48 + 16))[q];
        ulonglong2 wr = ((const ulonglong2*)(s_tv + k * 48 + 32))[q];
        at0 = ffma2(xxa, wt.x, at0); at1 = ffma2(xxa, wt.y, at1);
        ae0 = ffma2(xxa, we.x, ae0); ae1 = ffma2(xxa, we.y, ae1);
        ar0 = ffma2(xxa, wr.x, ar0); ar1 = ffma2(xxa, wr.y, ar1);
        bt0 = ffma2(xxb, wt.x, bt0); bt1 = ffma2(xxb, wt.y, bt1);
        be0 = ffma2(xxb, we.x, be0); be1 = ffma2(xxb, we.y, be1);
        br0 = ffma2(xxb, wr.x, br0); br1 = ffma2(xxb, wr.y, br1);
    }
    {
        u64 CC0 = pk2(C0, C0), CC1 = pk2(C1, C1);
        at0 = mul2(at0, CC0); at1 = mul2(at1, CC0);
        ae0 = mul2(ae0, CC0); ae1 = mul2(ae1, CC0);
        ar0 = mul2(ar0, CC0); ar1 = mul2(ar1, CC0);
        bt0 = mul2(bt0, CC1); bt1 = mul2(bt1, CC1);
        be0 = mul2(be0, CC1); be1 = mul2(be1, CC1);
        br0 = mul2(br0, CC1); br1 = mul2(br1, CC1);
    }

    // vector updates (per x component, both edges)
    #pragma unroll
    for (int x = 0; x < 3; x++) {
        float va = vctr[(size_t)e0 * 3 + x];
        float vbs = vctr[(size_t)e1 * 3 + x];
        u64 vxa = pk2(va, va), vxb = pk2(vbs, vbs);

        ulonglong2 eva = ((const ulonglong2*)(edge_v + (size_t)e0 * 48 + x * 16))[q];
        ulonglong2 nva = __ldg((const ulonglong2*)(g_nv + (size_t)s0 * 48 + x * 16) + q);
        u64 ua0 = ffma2(eva.x, at0, ffma2(nva.x, ae0, mul2(vxa, ar0)));
        u64 ua1 = ffma2(eva.y, at1, ffma2(nva.y, ae1, mul2(vxa, ar1)));
        ulonglong2 oa; oa.x = add2(ua0, eva.x); oa.y = add2(ua1, eva.y);
        ((ulonglong2*)(out_ev + (size_t)e0 * 48 + x * 16))[q] = oa;
        float2 p0 = upk(ua0), p1 = upk(ua1);
        red4(g_acc_v + (size_t)d0 * 48 + x * 16 + q * 4, p0.x, p0.y, p1.x, p1.y);

        ulonglong2 evb = ((const ulonglong2*)(edge_v + (size_t)e1 * 48 + x * 16))[q];
        ulonglong2 nvb = __ldg((const ulonglong2*)(g_nv + (size_t)s1 * 48 + x * 16) + q);
        u64 ub0 = ffma2(evb.x, bt0, ffma2(nvb.x, be0, mul2(vxb, br0)));
        u64 ub1 = ffma2(evb.y, bt1, ffma2(nvb.y, be1, mul2(vxb, br1)));
        ulonglong2 ob; ob.x = add2(ub0, evb.x); ob.y = add2(ub1, evb.y);
        ((ulonglong2*)(out_ev + (size_t)e1 * 48 + x * 16))[q] = ob;
        float2 r0 = upk(ub0), r1 = upk(ub1);
        red4(g_acc_v + (size_t)d1 * 48 + x * 16 + q * 4, r0.x, r0.y, r1.x, r1.y);
    }
}

// ============================================================================
// Kernel 3: node epilogue (unchanged)
// ============================================================================
#define K3_NPB 16
__global__ void __launch_bounds__(256) k_node_out(
    const float* __restrict__ node_s, const float* __restrict__ node_v,
    const float* __restrict__ onw,
    const float* __restrict__ w1, const float* __restrict__ b1,
    const float* __restrict__ w2, const float* __restrict__ b2,
    const float* __restrict__ gamma, const float* __restrict__ beta,
    const float* __restrict__ cns, float* __restrict__ out)
{
    __shared__ __align__(16) float s_w1[512], s_w2[2048], s_onw[2048];
    __shared__ float s_b1[16], s_b2[128], s_gam[128], s_bet[128], s_cns[128];
    __shared__ float sacc[2][16], snvn[2][16], sh[2][16], saccv[2][48];
    __shared__ float rs1[2][4], rs2[2][4];

    int t = threadIdx.x;
    for (int i = t; i < 512; i += 256) s_w1[i] = w1[i];
    for (int i = t; i < 2048; i += 256) { s_w2[i] = w2[i]; s_onw[i] = onw[i]; }
    if (t < 16) s_b1[t] = b1[t];
    if (t < 128) { s_b2[t] = b2[t]; s_gam[t] = gamma[t]; s_bet[t] = beta[t]; s_cns[t] = cns[t]; }
    __syncthreads();

    int grp = t >> 7, tt = t & 127;
    int n0 = blockIdx.x * K3_NPB;

    for (int it = 0; it < K3_NPB; it += 2) {
        int n = n0 + it + grp;

        if (tt < 16) sacc[grp][tt] = g_acc_s[(size_t)n * 16 + tt];
        else if (tt < 64) saccv[grp][tt - 16] = g_acc_v[(size_t)n * 48 + (tt - 16)];
        else if (tt < 80) {
            int l = tt - 64;
            float a = g_nv[(size_t)n * 48 + l];
            float b = g_nv[(size_t)n * 48 + 16 + l];
            float c = g_nv[(size_t)n * 48 + 32 + l];
            snvn[grp][l] = sqrtf(a * a + b * b + c * c);
        }
        __syncthreads();

        if (tt < 16) {
            float acc = s_b1[tt];
            #pragma unroll
            for (int k = 0; k < 16; k++) acc += sacc[grp][k] * s_w1[k * 16 + tt];
            #pragma unroll
            for (int k = 0; k < 16; k++) acc += snvn[grp][k] * s_w1[(16 + k) * 16 + tt];
            sh[grp][tt] = siluf(acc);
        }
        __syncthreads();

        float nsu = s_b2[tt];
        #pragma unroll
        for (int l = 0; l < 16; l++) nsu += sh[grp][l] * s_w2[l * 128 + tt];
        float xv = nsu + node_s[(size_t)n * 128 + tt];

        float s1 = xv, s2 = xv * xv;
        #pragma unroll
        for (int o = 16; o > 0; o >>= 1) {
            s1 += __shfl_down_sync(0xffffffffu, s1, o);
            s2 += __shfl_down_sync(0xffffffffu, s2, o);
        }
        if ((tt & 31) == 0) { rs1[grp][tt >> 5] = s1; rs2[grp][tt >> 5] = s2; }
        __syncthreads();
        float ts1 = rs1[grp][0] + rs1[grp][1] + rs1[grp][2] + rs1[grp][3];
        float ts2 = rs2[grp][0] + rs2[grp][1] + rs2[grp][2] + rs2[grp][3];
        float mu = ts1 * (1.f / 128.f);
        float var = ts2 * (1.f / 128.f) - mu * mu;
        out[(size_t)n * 128 + tt] = (xv - mu) * rsqrtf(var + 1e-5f) * s_gam[tt] + s_bet[tt];

        float a0 = 0.f, a1 = 0.f, a2 = 0.f;
        #pragma unroll
        for (int l = 0; l < 16; l++) {
            float w = s_onw[l * 128 + tt];
            a0 += saccv[grp][l] * w;
            a1 += saccv[grp][16 + l] * w;
            a2 += saccv[grp][32 + l] * w;
        }
        float v0 = a0 + node_v[(size_t)n * 384 + tt];
        float v1 = a1 + node_v[(size_t)n * 384 + 128 + tt];
        float v2 = a2 + node_v[(size_t)n * 384 + 256 + tt];
        float vn = sqrtf(v0 * v0 + v1 * v1 + v2 * v2);
        float sc = s_cns[tt] / (vn + 1e-8f);
        size_t base = 6400000ull + (size_t)n * 384;
        out[base + tt]       = v0 * sc;
        out[base + 128 + tt] = v1 * sc;
        out[base + 256 + tt] = v2 * sc;
        __syncthreads();
    }
}

// ============================================================================
extern "C" void kernel_launch(void* const* d_in, const int* in_sizes, int n_in,
                              void* d_out, int out_size)
{
    const float* node_s  = (const float*)d_in[0];
    const float* node_v  = (const float*)d_in[1];
    const float* edge_s  = (const float*)d_in[2];
    const float* edge_v  = (const float*)d_in[3];
    const float* dist    = (const float*)d_in[4];
    const float* vctr    = (const float*)d_in[5];
    const int*   src     = (const int*)d_in[6];
    const int*   dst     = (const int*)d_in[7];
    const float* ns_in_w = (const float*)d_in[8];
    const float* ns_in_b = (const float*)d_in[9];
    const float* nv_in_w = (const float*)d_in[10];
    const float* en_w    = (const float*)d_in[11];
    const float* en_b    = (const float*)d_in[12];
    const float* tp_w    = (const float*)d_in[13];
    const float* tp_b    = (const float*)d_in[14];
    const float* gate_w1 = (const float*)d_in[15];
    const float* gate_b1 = (const float*)d_in[16];
    const float* gate_w2 = (const float*)d_in[17];
    const float* gate_b2 = (const float*)d_in[18];
    const float* tv_w    = (const float*)d_in[19];
    const float* tv_b    = (const float*)d_in[20];
    const float* out_nv_w= (const float*)d_in[21];
    const float* ons_w1  = (const float*)d_in[22];
    const float* ons_b1  = (const float*)d_in[23];
    const float* ons_w2  = (const float*)d_in[24];
    const float* ons_b2  = (const float*)d_in[25];
    const float* ln_gamma= (const float*)d_in[26];
    const float* ln_beta = (const float*)d_in[27];
    const float* cn_scale= (const float*)d_in[28];

    float* out = (float*)d_out;
    float* out_es = out + 25600000ull;
    float* out_ev = out + 51200000ull;

    k_node_in<<<K1_BLOCKS, 256>>>(node_s, node_v, ns_in_w, ns_in_b, nv_in_w, en_w, en_b);
    k_edge<<<N_EDGES / 128, 256>>>(edge_s, edge_v, dist, vctr, src, dst,
                                   tp_w, tp_b, gate_w1, gate_b1, gate_w2, gate_b2,
                                   tv_w, tv_b, out_es, out_ev);
    k_node_out<<<N_NODES / K3_NPB, 256>>>(node_s, node_v, out_nv_w, ons_w1, ons_b1,
                                          ons_w2, ons_b2, ln_gamma, ln_beta, cn_scale, out);
}

// round 8
// speedup vs baseline: 1.6368x; 1.1024x over previous
#include <cuda_runtime.h>
#include <math.h>
#include <stdint.h>

#define N_NODES 50000
#define N_EDGES 1600000
#define G 128
#define LG 16
#define PI_F 3.14159265358979323846f

typedef unsigned long long u64;

// ---- scratch (device globals; no allocation allowed) ----
__device__ __align__(16) float g_a[N_NODES * LG];
__device__ __align__(16) float g_b[N_NODES * LG];
__device__ __align__(16) float g_nv[N_NODES * 3 * LG];
__device__ __align__(16) float g_acc_s[N_NODES * LG];
__device__ __align__(16) float g_acc_v[N_NODES * 3 * LG];

__device__ __forceinline__ float siluf(float x) { return x / (1.f + __expf(-x)); }

__device__ __forceinline__ void red4(float* p, float a, float b, float c, float d) {
    asm volatile("red.global.add.v4.f32 [%0], {%1,%2,%3,%4};"
                 :: "l"(p), "f"(a), "f"(b), "f"(c), "f"(d) : "memory");
}

// ---- packed f32x2 helpers ----
__device__ __forceinline__ u64 ffma2(u64 a, u64 b, u64 c) {
    u64 d; asm("fma.rn.f32x2 %0,%1,%2,%3;" : "=l"(d) : "l"(a), "l"(b), "l"(c)); return d;
}
__device__ __forceinline__ u64 mul2(u64 a, u64 b) {
    u64 d; asm("mul.rn.f32x2 %0,%1,%2;" : "=l"(d) : "l"(a), "l"(b)); return d;
}
__device__ __forceinline__ u64 add2(u64 a, u64 b) {
    u64 d; asm("add.rn.f32x2 %0,%1,%2;" : "=l"(d) : "l"(a), "l"(b)); return d;
}
__device__ __forceinline__ u64 pk2(float x, float y) {
    u64 r; asm("mov.b64 %0,{%1,%2};" : "=l"(r) : "f"(x), "f"(y)); return r;
}
__device__ __forceinline__ float2 upk(u64 a) {
    float lo, hi; asm("mov.b64 {%0,%1},%2;" : "=f"(lo), "=f"(hi) : "l"(a));
    return make_float2(lo, hi);
}

// ============================================================================
// Kernel 1: node input projections (unchanged from R6/R7 — ~70us)
// ============================================================================
#define WPAD 130
#define K1_TILES ((N_NODES + 31) / 32)
#define K1_BLOCKS 592

__global__ void __launch_bounds__(256) k_node_in(
    const float* __restrict__ node_s, const float* __restrict__ node_v,
    const float* __restrict__ ns_w, const float* __restrict__ ns_b,
    const float* __restrict__ nv_w, const float* __restrict__ en_w,
    const float* __restrict__ en_b)
{
    __shared__ __align__(16) float s_wsT[16 * WPAD];
    __shared__ __align__(16) float s_wvT[16 * WPAD];
    __shared__ __align__(16) float s_en[512];
    __shared__ float s_sns[32 * 16];
    __shared__ float s_nsb[16], s_enb[16];

    int t = threadIdx.x;

    {
        float4* as4 = (float4*)g_acc_s;
        float4* av4 = (float4*)g_acc_v;
        int idx = blockIdx.x * 256 + t;
        int stride = K1_BLOCKS * 256;
        for (int i = idx; i < 200000; i += stride) as4[i] = make_float4(0.f, 0.f, 0.f, 0.f);
        for (int i = idx; i < 600000; i += stride) av4[i] = make_float4(0.f, 0.f, 0.f, 0.f);
    }

    for (int i = t; i < 2048; i += 256) {
        int gg = i >> 4, j = i & 15;
        s_wsT[j * WPAD + gg] = ns_w[i];
        s_wvT[j * WPAD + gg] = nv_w[i];
    }
    for (int i = t; i < 512; i += 256) s_en[i] = en_w[i];
    if (t < 16) { s_nsb[t] = ns_b[t]; s_enb[t] = en_b[t]; }
    __syncthreads();

    int j = t & 7, slot = t >> 3;
    const float2* wsA = (const float2*)(s_wsT + j * WPAD);
    const float2* wsB = (const float2*)(s_wsT + (j + 8) * WPAD);
    const float2* wvA = (const float2*)(s_wvT + j * WPAD);
    const float2* wvB = (const float2*)(s_wvT + (j + 8) * WPAD);

    for (int tile = blockIdx.x; tile < K1_TILES; tile += K1_BLOCKS) {
        int n = tile * 32 + slot;
        bool ok = (n < N_NODES);

        if (ok) {
            {
                const float4* r4 = (const float4*)(node_s + (size_t)n * 128);
                float aA0 = 0.f, aA1 = 0.f, aB0 = 0.f, aB1 = 0.f;
                #pragma unroll 8
                for (int qq = 0; qq < 32; qq++) {
                    float4 r = __ldg(r4 + qq);
                    float2 wa = wsA[2 * qq], wb = wsA[2 * qq + 1];
                    float2 wc = wsB[2 * qq], wd = wsB[2 * qq + 1];
                    aA0 += r.x * wa.x + r.y * wa.y; aA1 += r.z * wb.x + r.w * wb.y;
                    aB0 += r.x * wc.x + r.y * wc.y; aB1 += r.z * wd.x + r.w * wd.y;
                }
                s_sns[slot * 16 + j]     = siluf(aA0 + aA1 + s_nsb[j]);
                s_sns[slot * 16 + j + 8] = siluf(aB0 + aB1 + s_nsb[j + 8]);
            }
            {
                const float4* v0 = (const float4*)(node_v + (size_t)n * 384);
                const float4* v1 = v0 + 32;
                const float4* v2 = v0 + 64;
                float a0A = 0.f, a1A = 0.f, a2A = 0.f;
                float a0B = 0.f, a1B = 0.f, a2B = 0.f;
                #pragma unroll 8
                for (int qq = 0; qq < 32; qq++) {
                    float2 wa = wvA[2 * qq], wb = wvA[2 * qq + 1];
                    float2 wc = wvB[2 * qq], wd = wvB[2 * qq + 1];
                    float4 r0 = __ldg(v0 + qq), r1 = __ldg(v1 + qq), r2 = __ldg(v2 + qq);
                    a0A += r0.x * wa.x + r0.y * wa.y + r0.z * wb.x + r0.w * wb.y;
                    a1A += r1.x * wa.x + r1.y * wa.y + r1.z * wb.x + r1.w * wb.y;
                    a2A += r2.x * wa.x + r2.y * wa.y + r2.z * wb.x + r2.w * wb.y;
                    a0B += r0.x * wc.x + r0.y * wc.y + r0.z * wd.x + r0.w * wd.y;
                    a1B += r1.x * wc.x + r1.y * wc.y + r1.z * wd.x + r1.w * wd.y;
                    a2B += r2.x * wc.x + r2.y * wc.y + r2.z * wd.x + r2.w * wd.y;
                }
                g_nv[(size_t)n * 48 + j]          = a0A;
                g_nv[(size_t)n * 48 + 16 + j]     = a1A;
                g_nv[(size_t)n * 48 + 32 + j]     = a2A;
                g_nv[(size_t)n * 48 + j + 8]      = a0B;
                g_nv[(size_t)n * 48 + 16 + j + 8] = a1B;
                g_nv[(size_t)n * 48 + 32 + j + 8] = a2B;
            }
        }
        __syncthreads();

        if (ok) {
            float aA = 0.f, bA = s_enb[j];
            float aB = 0.f, bB = s_enb[j + 8];
            #pragma unroll
            for (int k = 0; k < 16; k++) {
                float x = s_sns[slot * 16 + k];
                aA += x * s_en[k * 16 + j];
                bA += x * s_en[(16 + k) * 16 + j];
                aB += x * s_en[k * 16 + j + 8];
                bB += x * s_en[(16 + k) * 16 + j + 8];
            }
            g_a[(size_t)n * 16 + j]     = aA;
            g_b[(size_t)n * 16 + j]     = bA;
            g_a[(size_t)n * 16 + j + 8] = aB;
            g_b[(size_t)n * 16 + j + 8] = bB;
        }
        __syncthreads();
    }
}

// ============================================================================
// Kernel 2: QUAD layout, 4 EDGES PER THREAD — each weight LDS.128 feeds 16
// FFMA2. 128 threads/block = 32 quads; thread handles edges
// e[m] = blk*128 + slot + 32*m, m=0..3.
// ============================================================================
#define NE 4

// Y[m][0..1] += x[m] @ W (one weight LDS per k for all 4 edges)
#define Q_MATVEC(Y, X, SW, Q)                                                \
    {                                                                        \
        _Pragma("unroll")                                                    \
        for (int k = 0; k < 16; k++) {                                       \
            ulonglong2 w = ((const ulonglong2*)((SW) + k * 16))[Q];          \
            _Pragma("unroll")                                                \
            for (int m = 0; m < NE; m++) {                                   \
                float2 xp = upk(X[m][(k >> 1) & 1]);                         \
                float xs = (k & 1) ? xp.y : xp.x;                            \
                float xk = __shfl_sync(0xffffffffu, xs, k >> 2, 4);          \
                u64 xx = pk2(xk, xk);                                        \
                Y[m][0] = ffma2(xx, w.x, Y[m][0]);                           \
                Y[m][1] = ffma2(xx, w.y, Y[m][1]);                           \
            }                                                                \
        }                                                                    \
    }

__global__ void __launch_bounds__(128, 4) k_edge(
    const float* __restrict__ edge_s, const float* __restrict__ edge_v,
    const float* __restrict__ dist,   const float* __restrict__ vctr,
    const int* __restrict__ src,      const int* __restrict__ dst,
    const float* __restrict__ tp_w, const float* __restrict__ tp_b,
    const float* __restrict__ g1w,  const float* __restrict__ g1b,
    const float* __restrict__ g2w,  const float* __restrict__ g2b,
    const float* __restrict__ tvw,  const float* __restrict__ tvb,
    float* __restrict__ out_es, float* __restrict__ out_ev)
{
    __shared__ __align__(16) float s_tp[256], s_g1[256], s_g2[256], s_tv[768];
    __shared__ __align__(16) float s_tpb[16], s_g1b[16], s_g2b[16], s_tvb[48];
    int t = threadIdx.x;
    for (int i = t; i < 256; i += 128) { s_tp[i] = tp_w[i]; s_g1[i] = g1w[i]; s_g2[i] = g2w[i]; }
    for (int i = t; i < 768; i += 128) s_tv[i] = tvw[i];
    if (t < 16) { s_tpb[t] = tp_b[t]; s_g1b[t] = g1b[t]; s_g2b[t] = g2b[t]; }
    if (t < 48) s_tvb[t] = tvb[t];
    __syncthreads();

    int q = t & 3;
    int slot = t >> 2;                      // 0..31
    int eb = blockIdx.x * 128 + slot;

    int sa[NE], da[NE];
    float ddv[NE];
    #pragma unroll
    for (int m = 0; m < NE; m++) {
        int e = eb + 32 * m;
        sa[m] = src[e]; da[m] = dst[e]; ddv[m] = dist[e];
    }

    // edge_s rows
    u64 esl[NE][2];
    #pragma unroll
    for (int m = 0; m < NE; m++) {
        ulonglong2 v = ((const ulonglong2*)edge_s)[(size_t)(eb + 32 * m) * 4 + q];
        esl[m][0] = v.x; esl[m][1] = v.y;
    }

    // gathers: a[src]+b[dst]
    u64 en[NE][2];
    #pragma unroll
    for (int m = 0; m < NE; m++) {
        ulonglong2 va = __ldg((const ulonglong2*)g_a + (size_t)sa[m] * 4 + q);
        ulonglong2 vb = __ldg((const ulonglong2*)g_b + (size_t)da[m] * 4 + q);
        en[m][0] = add2(va.x, vb.x); en[m][1] = add2(va.y, vb.y);
    }

    // tm = en * (edge_s @ tp_w + tp_b)
    u64 tm[NE][2];
    {
        ulonglong2 b = ((const ulonglong2*)s_tpb)[q];
        #pragma unroll
        for (int m = 0; m < NE; m++) { tm[m][0] = b.x; tm[m][1] = b.y; }
    }
    Q_MATVEC(tm, esl, s_tp, q);
    #pragma unroll
    for (int m = 0; m < NE; m++) {
        tm[m][0] = mul2(tm[m][0], en[m][0]);
        tm[m][1] = mul2(tm[m][1], en[m][1]);
    }

    // h = silu(tm @ g1 + b1)
    u64 h[NE][2];
    {
        ulonglong2 b = ((const ulonglong2*)s_g1b)[q];
        #pragma unroll
        for (int m = 0; m < NE; m++) { h[m][0] = b.x; h[m][1] = b.y; }
    }
    Q_MATVEC(h, tm, s_g1, q);
    #pragma unroll
    for (int m = 0; m < NE; m++) {
        float2 a = upk(h[m][0]), b = upk(h[m][1]);
        h[m][0] = pk2(siluf(a.x), siluf(a.y));
        h[m][1] = pk2(siluf(b.x), siluf(b.y));
    }

    // gt = h @ g2 + b2
    u64 gt[NE][2];
    {
        ulonglong2 b = ((const ulonglong2*)s_g2b)[q];
        #pragma unroll
        for (int m = 0; m < NE; m++) { gt[m][0] = b.x; gt[m][1] = b.y; }
    }
    Q_MATVEC(gt, h, s_g2, q);

    float Cv[NE];
    #pragma unroll
    for (int m = 0; m < NE; m++)
        Cv[m] = 0.5f * (__cosf(PI_F * ddv[m] * 0.1f) + 1.f) * (ddv[m] < 10.f ? 1.f : 0.f);

    // es = tm * sigmoid(gt) * C ; write edge_s_out ; scatter acc_s
    u64 es[NE][2];
    #pragma unroll
    for (int m = 0; m < NE; m++) {
        float2 tv0 = upk(tm[m][0]), tv1 = upk(tm[m][1]);
        float2 gv0 = upk(gt[m][0]), gv1 = upk(gt[m][1]);
        es[m][0] = pk2(tv0.x * (1.f / (1.f + __expf(-gv0.x))) * Cv[m],
                       tv0.y * (1.f / (1.f + __expf(-gv0.y))) * Cv[m]);
        es[m][1] = pk2(tv1.x * (1.f / (1.f + __expf(-gv1.x))) * Cv[m],
                       tv1.y * (1.f / (1.f + __expf(-gv1.y))) * Cv[m]);
        ulonglong2 o;
        o.x = add2(es[m][0], esl[m][0]);
        o.y = add2(es[m][1], esl[m][1]);
        ((ulonglong2*)out_es)[(size_t)(eb + 32 * m) * 4 + q] = o;
        float2 a = upk(es[m][0]), b = upk(es[m][1]);
        red4(g_acc_s + (size_t)da[m] * 16 + q * 4, a.x, a.y, b.x, b.y);
    }

    // ter = (es @ tv_w + tv_b) * C ; lane holds its 4 channels of t/e/r per edge
    u64 ter[NE][6];   // [t0,t1,e0,e1,r0,r1]
    {
        ulonglong2 w0 = ((const ulonglong2*)(s_tvb))[q];
        ulonglong2 w1 = ((const ulonglong2*)(s_tvb + 16))[q];
        ulonglong2 w2 = ((const ulonglong2*)(s_tvb + 32))[q];
        #pragma unroll
        for (int m = 0; m < NE; m++) {
            ter[m][0] = w0.x; ter[m][1] = w0.y;
            ter[m][2] = w1.x; ter[m][3] = w1.y;
            ter[m][4] = w2.x; ter[m][5] = w2.y;
        }
    }
    #pragma unroll
    for (int k = 0; k < 16; k++) {
        ulonglong2 wt = ((const ulonglong2*)(s_tv + k * 48))[q];
        ulonglong2 we = ((const ulonglong2*)(s_tv + k * 48 + 16))[q];
        ulonglong2 wr = ((const ulonglong2*)(s_tv + k * 48 + 32))[q];
        #pragma unroll
        for (int m = 0; m < NE; m++) {
            float2 xp = upk(es[m][(k >> 1) & 1]);
            float xs = (k & 1) ? xp.y : xp.x;
            float xk = __shfl_sync(0xffffffffu, xs, k >> 2, 4);
            u64 xx = pk2(xk, xk);
            ter[m][0] = ffma2(xx, wt.x, ter[m][0]);
            ter[m][1] = ffma2(xx, wt.y, ter[m][1]);
            ter[m][2] = ffma2(xx, we.x, ter[m][2]);
            ter[m][3] = ffma2(xx, we.y, ter[m][3]);
            ter[m][4] = ffma2(xx, wr.x, ter[m][4]);
            ter[m][5] = ffma2(xx, wr.y, ter[m][5]);
        }
    }
    #pragma unroll
    for (int m = 0; m < NE; m++) {
        u64 CC = pk2(Cv[m], Cv[m]);
        #pragma unroll
        for (int i = 0; i < 6; i++) ter[m][i] = mul2(ter[m][i], CC);
    }

    // vector updates: per x component, per edge
    #pragma unroll
    for (int x = 0; x < 3; x++) {
        #pragma unroll
        for (int m = 0; m < NE; m++) {
            int e = eb + 32 * m;
            float vc = vctr[(size_t)e * 3 + x];
            u64 vx = pk2(vc, vc);
            ulonglong2 ev = ((const ulonglong2*)(edge_v + (size_t)e * 48 + x * 16))[q];
            ulonglong2 nv = __ldg((const ulonglong2*)(g_nv + (size_t)sa[m] * 48 + x * 16) + q);
            u64 u0 = ffma2(ev.x, ter[m][0], ffma2(nv.x, ter[m][2], mul2(vx, ter[m][4])));
            u64 u1 = ffma2(ev.y, ter[m][1], ffma2(nv.y, ter[m][3], mul2(vx, ter[m][5])));
            ulonglong2 o; o.x = add2(u0, ev.x); o.y = add2(u1, ev.y);
            ((ulonglong2*)(out_ev + (size_t)e * 48 + x * 16))[q] = o;
            float2 a = upk(u0), b = upk(u1);
            red4(g_acc_v + (size_t)da[m] * 48 + x * 16 + q * 4, a.x, a.y, b.x, b.y);
        }
    }
}

// ============================================================================
// Kernel 3: node epilogue (unchanged)
// ============================================================================
#define K3_NPB 16
__global__ void __launch_bounds__(256) k_node_out(
    const float* __restrict__ node_s, const float* __restrict__ node_v,
    const float* __restrict__ onw,
    const float* __restrict__ w1, const float* __restrict__ b1,
    const float* __restrict__ w2, const float* __restrict__ b2,
    const float* __restrict__ gamma, const float* __restrict__ beta,
    const float* __restrict__ cns, float* __restrict__ out)
{
    __shared__ __align__(16) float s_w1[512], s_w2[2048], s_onw[2048];
    __shared__ float s_b1[16], s_b2[128], s_gam[128], s_bet[128], s_cns[128];
    __shared__ float sacc[2][16], snvn[2][16], sh[2][16], saccv[2][48];
    __shared__ float rs1[2][4], rs2[2][4];

    int t = threadIdx.x;
    for (int i = t; i < 512; i += 256) s_w1[i] = w1[i];
    for (int i = t; i < 2048; i += 256) { s_w2[i] = w2[i]; s_onw[i] = onw[i]; }
    if (t < 16) s_b1[t] = b1[t];
    if (t < 128) { s_b2[t] = b2[t]; s_gam[t] = gamma[t]; s_bet[t] = beta[t]; s_cns[t] = cns[t]; }
    __syncthreads();

    int grp = t >> 7, tt = t & 127;
    int n0 = blockIdx.x * K3_NPB;

    for (int it = 0; it < K3_NPB; it += 2) {
        int n = n0 + it + grp;

        if (tt < 16) sacc[grp][tt] = g_acc_s[(size_t)n * 16 + tt];
        else if (tt < 64) saccv[grp][tt - 16] = g_acc_v[(size_t)n * 48 + (tt - 16)];
        else if (tt < 80) {
            int l = tt - 64;
            float a = g_nv[(size_t)n * 48 + l];
            float b = g_nv[(size_t)n * 48 + 16 + l];
            float c = g_nv[(size_t)n * 48 + 32 + l];
            snvn[grp][l] = sqrtf(a * a + b * b + c * c);
        }
        __syncthreads();

        if (tt < 16) {
            float acc = s_b1[tt];
            #pragma unroll
            for (int k = 0; k < 16; k++) acc += sacc[grp][k] * s_w1[k * 16 + tt];
            #pragma unroll
            for (int k = 0; k < 16; k++) acc += snvn[grp][k] * s_w1[(16 + k) * 16 + tt];
            sh[grp][tt] = siluf(acc);
        }
        __syncthreads();

        float nsu = s_b2[tt];
        #pragma unroll
        for (int l = 0; l < 16; l++) nsu += sh[grp][l] * s_w2[l * 128 + tt];
        float xv = nsu + node_s[(size_t)n * 128 + tt];

        float s1 = xv, s2 = xv * xv;
        #pragma unroll
        for (int o = 16; o > 0; o >>= 1) {
            s1 += __shfl_down_sync(0xffffffffu, s1, o);
            s2 += __shfl_down_sync(0xffffffffu, s2, o);
        }
        if ((tt & 31) == 0) { rs1[grp][tt >> 5] = s1; rs2[grp][tt >> 5] = s2; }
        __syncthreads();
        float ts1 = rs1[grp][0] + rs1[grp][1] + rs1[grp][2] + rs1[grp][3];
        float ts2 = rs2[grp][0] + rs2[grp][1] + rs2[grp][2] + rs2[grp][3];
        float mu = ts1 * (1.f / 128.f);
        float var = ts2 * (1.f / 128.f) - mu * mu;
        out[(size_t)n * 128 + tt] = (xv - mu) * rsqrtf(var + 1e-5f) * s_gam[tt] + s_bet[tt];

        float a0 = 0.f, a1 = 0.f, a2 = 0.f;
        #pragma unroll
        for (int l = 0; l < 16; l++) {
            float w = s_onw[l * 128 + tt];
            a0 += saccv[grp][l] * w;
            a1 += saccv[grp][16 + l] * w;
            a2 += saccv[grp][32 + l] * w;
        }
        float v0 = a0 + node_v[(size_t)n * 384 + tt];
        float v1 = a1 + node_v[(size_t)n * 384 + 128 + tt];
        float v2 = a2 + node_v[(size_t)n * 384 + 256 + tt];
        float vn = sqrtf(v0 * v0 + v1 * v1 + v2 * v2);
        float sc = s_cns[tt] / (vn + 1e-8f);
        size_t base = 6400000ull + (size_t)n * 384;
        out[base + tt]       = v0 * sc;
        out[base + 128 + tt] = v1 * sc;
        out[base + 256 + tt] = v2 * sc;
        __syncthreads();
    }
}

// ============================================================================
extern "C" void kernel_launch(void* const* d_in, const int* in_sizes, int n_in,
                              void* d_out, int out_size)
{
    const float* node_s  = (const float*)d_in[0];
    const float* node_v  = (const float*)d_in[1];
    const float* edge_s  = (const float*)d_in[2];
    const float* edge_v  = (const float*)d_in[3];
    const float* dist    = (const float*)d_in[4];
    const float* vctr    = (const float*)d_in[5];
    const int*   src     = (const int*)d_in[6];
    const int*   dst     = (const int*)d_in[7];
    const float* ns_in_w = (const float*)d_in[8];
    const float* ns_in_b = (const float*)d_in[9];
    const float* nv_in_w = (const float*)d_in[10];
    const float* en_w    = (const float*)d_in[11];
    const float* en_b    = (const float*)d_in[12];
    const float* tp_w    = (const float*)d_in[13];
    const float* tp_b    = (const float*)d_in[14];
    const float* gate_w1 = (const float*)d_in[15];
    const float* gate_b1 = (const float*)d_in[16];
    const float* gate_w2 = (const float*)d_in[17];
    const float* gate_b2 = (const float*)d_in[18];
    const float* tv_w    = (const float*)d_in[19];
    const float* tv_b    = (const float*)d_in[20];
    const float* out_nv_w= (const float*)d_in[21];
    const float* ons_w1  = (const float*)d_in[22];
    const float* ons_b1  = (const float*)d_in[23];
    const float* ons_w2  = (const float*)d_in[24];
    const float* ons_b2  = (const float*)d_in[25];
    const float* ln_gamma= (const float*)d_in[26];
    const float* ln_beta = (const float*)d_in[27];
    const float* cn_scale= (const float*)d_in[28];

    float* out = (float*)d_out;
    float* out_es = out + 25600000ull;
    float* out_ev = out + 51200000ull;

    k_node_in<<<K1_BLOCKS, 256>>>(node_s, node_v, ns_in_w, ns_in_b, nv_in_w, en_w, en_b);
    k_edge<<<N_EDGES / 128, 128>>>(edge_s, edge_v, dist, vctr, src, dst,
                                   tp_w, tp_b, gate_w1, gate_b1, gate_w2, gate_b2,
                                   tv_w, tv_b, out_es, out_ev);
    k_node_out<<<N_NODES / K3_NPB, 256>>>(node_s, node_v, out_nv_w, ons_w1, ons_b1,
                                          ons_w2, ons_b2, ln_gamma, ln_beta, cn_scale, out);
}